// round 1
// baseline (speedup 1.0000x reference)
#include <cuda_runtime.h>
#include <math.h>

#define BATCH 32
#define NN    2000
#define TD    384
#define EMB   64

// scratch for layernormed q/k projections: 16.4 MB each
__device__ float g_Q[BATCH * NN * EMB];
__device__ float g_K[BATCH * NN * EMB];

// ---------------------------------------------------------------------------
// Kernel 1: fused  q = LN(xf@Wq+bq), k = LN(xf@Wk+bk)
// block = 256 threads handles 64 rows (row = b*2000+n flattened).
// thread (rg = tid>>4, og = tid&15) owns 4 rows x 8 outputs (outputs og+16j;
// j<4 -> q[0..63], j>=4 -> k[0..63]).
// ---------------------------------------------------------------------------
__global__ __launch_bounds__(256) void k_proj(
    const float* __restrict__ x,
    const float* __restrict__ Wq, const float* __restrict__ bq,
    const float* __restrict__ Wk, const float* __restrict__ bk,
    const float* __restrict__ g0, const float* __restrict__ be0,
    const float* __restrict__ g1, const float* __restrict__ be1)
{
    __shared__ float xs[64][33];    // 64 rows x 32 e-chunk (+1 pad)
    __shared__ float ws[32][128];   // 32 e x (64 q-outs | 64 k-outs)

    const int tid = threadIdx.x;
    const int rg  = tid >> 4;   // 0..15 -> rows rg*4 .. rg*4+3
    const int og  = tid & 15;   // 0..15
    const long R0 = (long)blockIdx.x * 64;

    float acc[4][8];
#pragma unroll
    for (int i = 0; i < 4; i++)
#pragma unroll
        for (int j = 0; j < 8; j++) acc[i][j] = 0.f;

    for (int ch = 0; ch < 12; ch++) {
        // load x chunk: 64 rows x 32 cols, coalesced
#pragma unroll
        for (int p = 0; p < 8; p++) {
            int row = (tid >> 5) + 8 * p;
            int c   = tid & 31;
            xs[row][c] = x[(R0 + row) * 384 + ch * 32 + c];
        }
        // load W chunk: 32 e x 128 outs
#pragma unroll
        for (int p = 0; p < 16; p++) {
            int idx = tid + 256 * p;
            int e = idx >> 7, o = idx & 127;
            float v = (o < 64) ? Wq[(ch * 32 + e) * 64 + o]
                               : Wk[(ch * 32 + e) * 64 + (o - 64)];
            ws[e][o] = v;
        }
        __syncthreads();

#pragma unroll 4
        for (int e = 0; e < 32; e++) {
            float xv[4];
#pragma unroll
            for (int i = 0; i < 4; i++) xv[i] = xs[rg * 4 + i][e];
#pragma unroll
            for (int j = 0; j < 8; j++) {
                float wv = ws[e][og + 16 * j];
#pragma unroll
                for (int i = 0; i < 4; i++) acc[i][j] += xv[i] * wv;
            }
        }
        __syncthreads();
    }

    // bias + per-row layernorm.  Each row is owned by a 16-lane half-warp
    // (lanes share rg), so reduce with width-16 shuffles.
#pragma unroll
    for (int i = 0; i < 4; i++) {
        int row = rg * 4 + i;
        float vq[4], vk[4];
#pragma unroll
        for (int j = 0; j < 4; j++) {
            int o = og + 16 * j;
            vq[j] = acc[i][j]     + bq[o];
            vk[j] = acc[i][4 + j] + bk[o];
        }
        float qs = 0.f, qs2 = 0.f, ks = 0.f, ks2 = 0.f;
#pragma unroll
        for (int j = 0; j < 4; j++) {
            qs += vq[j]; qs2 += vq[j] * vq[j];
            ks += vk[j]; ks2 += vk[j] * vk[j];
        }
#pragma unroll
        for (int m = 8; m >= 1; m >>= 1) {
            qs  += __shfl_xor_sync(0xffffffffu, qs,  m, 16);
            qs2 += __shfl_xor_sync(0xffffffffu, qs2, m, 16);
            ks  += __shfl_xor_sync(0xffffffffu, ks,  m, 16);
            ks2 += __shfl_xor_sync(0xffffffffu, ks2, m, 16);
        }
        float mq = qs * (1.f / 64.f);
        float rq = rsqrtf(qs2 * (1.f / 64.f) - mq * mq + 1e-5f);
        float mk = ks * (1.f / 64.f);
        float rk = rsqrtf(ks2 * (1.f / 64.f) - mk * mk + 1e-5f);
        long base = (R0 + row) * 64;
#pragma unroll
        for (int j = 0; j < 4; j++) {
            int o = og + 16 * j;
            g_Q[base + o] = (vq[j] - mq) * rq * g0[o] + be0[o];
            g_K[base + o] = (vk[j] - mk) * rk * g1[o] + be1[o];
        }
    }
}

// ---------------------------------------------------------------------------
// Kernel 2: data = softmax(q kT / sqrt(NN)) @ normal  (streaming, no max needed
// since |score| <= 64/sqrt(2000) = 1.43: exp never overflows).
// grid (50 n-tiles of 40 rows, 32 batches). block 256.
// Accumulator: 40 rows x 384 cols fp32 in regs (warp w owns rows w*5..w*5+4,
// lane owns cols lane+32*jj, jj<12  => 60 regs/thread).
// m streamed in tiles of 50 (40 iterations).
// ---------------------------------------------------------------------------
#define BM 40
#define BK 50
#define SM2_FLOATS (BK * 384 + BM * 65 + BK * 65 + BM * BK)

__global__ __launch_bounds__(256, 2) void k_attn(
    const float* __restrict__ normal, float* __restrict__ out)
{
    extern __shared__ float sm[];
    float* Vs = sm;                              // [50][384], 16B aligned
    float* Qs = sm + BK * 384;                   // [40][65]
    float* Ks = Qs + BM * 65;                    // [50][65]
    float* Ps = Ks + BK * 65;                    // [40][50]

    const int tid  = threadIdx.x;
    const int wid  = tid >> 5;
    const int lane = tid & 31;
    const int b    = blockIdx.y;
    const int n0   = blockIdx.x * BM;
    const long qbase = (long)b * NN + n0;
    const float SCALE = 0.02236067977f;          // 1/sqrt(2000)

    // load Q tile (40 x 64)
    for (int idx = tid; idx < BM * 64; idx += 256) {
        int r = idx >> 6, e = idx & 63;
        Qs[r * 65 + e] = g_Q[(qbase + r) * 64 + e];
    }

    float acc[5][12];
#pragma unroll
    for (int i = 0; i < 5; i++)
#pragma unroll
        for (int j = 0; j < 12; j++) acc[i][j] = 0.f;
    float sums[5] = {0.f, 0.f, 0.f, 0.f, 0.f};

    const int r0 = wid * 5;

    for (int mt = 0; mt < NN / BK; mt++) {
        const int m0 = mt * BK;
        __syncthreads();
        // K tile (50 x 64)
        {
            const long kbase = (long)b * NN + m0;
            for (int idx = tid; idx < BK * 64; idx += 256) {
                int r = idx >> 6, e = idx & 63;
                Ks[r * 65 + e] = g_K[(kbase + r) * 64 + e];
            }
        }
        // V tile = normal rows m0..m0+49 (50 x 384), flat float4 copy
        {
            const float4* np = (const float4*)(normal + (long)m0 * 384);
            float4* vp = (float4*)Vs;
            for (int idx = tid; idx < BK * 96; idx += 256) vp[idx] = np[idx];
        }
        __syncthreads();

        // S = exp(Q K^T * SCALE): 100 threads, each 4 rows x 5 cols
        if (tid < 100) {
            const int rgi = tid / 10;   // 0..9  -> rows rgi*4..+3
            const int mgi = tid % 10;   // 0..9  -> ms   mgi*5..+4
            float s[4][5];
#pragma unroll
            for (int i = 0; i < 4; i++)
#pragma unroll
                for (int j = 0; j < 5; j++) s[i][j] = 0.f;
#pragma unroll 4
            for (int e = 0; e < 64; e++) {
                float qv[4], kv[5];
#pragma unroll
                for (int i = 0; i < 4; i++) qv[i] = Qs[(rgi * 4 + i) * 65 + e];
#pragma unroll
                for (int j = 0; j < 5; j++) kv[j] = Ks[(mgi * 5 + j) * 65 + e];
#pragma unroll
                for (int i = 0; i < 4; i++)
#pragma unroll
                    for (int j = 0; j < 5; j++) s[i][j] += qv[i] * kv[j];
            }
#pragma unroll
            for (int i = 0; i < 4; i++)
#pragma unroll
                for (int j = 0; j < 5; j++)
                    Ps[(rgi * 4 + i) * BK + mgi * 5 + j] = __expf(s[i][j] * SCALE);
        }
        __syncthreads();

        // PV accumulate: acc += P @ V, sums += row-sums(P)
#pragma unroll 2
        for (int k = 0; k < BK; k++) {
            float pv[5];
#pragma unroll
            for (int i = 0; i < 5; i++) {
                pv[i] = Ps[(r0 + i) * BK + k];
                sums[i] += pv[i];
            }
            float vv[12];
#pragma unroll
            for (int jj = 0; jj < 12; jj++) vv[jj] = Vs[k * 384 + lane + 32 * jj];
#pragma unroll
            for (int i = 0; i < 5; i++)
#pragma unroll
                for (int jj = 0; jj < 12; jj++) acc[i][jj] += pv[i] * vv[jj];
        }
    }

    // epilogue: data = acc / rowsum   (all lanes hold identical sums[i])
#pragma unroll
    for (int i = 0; i < 5; i++) {
        float inv = 1.f / sums[i];
        size_t base = (size_t)(qbase + r0 + i) * 384;
#pragma unroll
        for (int jj = 0; jj < 12; jj++)
            out[base + lane + 32 * jj] = acc[i][jj] * inv;
    }
}

// ---------------------------------------------------------------------------
// Kernel 3: time-attention weight + broadcast add (in place on out).
// warp per (b,n) node; block = 8 warps.
// ---------------------------------------------------------------------------
__global__ __launch_bounds__(256) void k_time(
    const float* __restrict__ x, const float* __restrict__ Win,
    float* __restrict__ out)
{
    const int wid = threadIdx.x >> 5, lane = threadIdx.x & 31;
    const long node = (long)blockIdx.x * 8 + wid;  // 0..63999
    __shared__ float qs[8][17];

    const float* xl = x + node * 384 + 368;   // x[b,n,23,:]
    float* dat = out + node * 384;

    if (lane < 16) {
        float q = 0.f;
#pragma unroll
        for (int d = 0; d < 16; d++) q += xl[d] * Win[d * 16 + lane];
        qs[wid][lane] = q;
    }
    __syncwarp();

    float att = -1e30f;
    if (lane < 24) {
        float a = 0.f;
#pragma unroll
        for (int d = 0; d < 16; d++) a += qs[wid][d] * dat[lane * 16 + d];
        att = a;
    }
    float mx = att;
#pragma unroll
    for (int m = 16; m >= 1; m >>= 1)
        mx = fmaxf(mx, __shfl_xor_sync(0xffffffffu, mx, m));
    float e = (lane < 24) ? __expf(att - mx) : 0.f;
    float s = e;
#pragma unroll
    for (int m = 16; m >= 1; m >>= 1)
        s += __shfl_xor_sync(0xffffffffu, s, m);
    float w = e / s;

#pragma unroll
    for (int jj = 0; jj < 12; jj++) {
        int i = lane + 32 * jj;
        int t = i >> 4;                 // timestep of this element (<24)
        float wt = __shfl_sync(0xffffffffu, w, t);
        dat[i] += wt;
    }
}

// ---------------------------------------------------------------------------
extern "C" void kernel_launch(void* const* d_in, const int* in_sizes, int n_in,
                              void* d_out, int out_size)
{
    const float* x      = (const float*)d_in[0];
    const float* Wq     = (const float*)d_in[1];
    const float* bq     = (const float*)d_in[2];
    const float* Wk     = (const float*)d_in[3];
    const float* bk     = (const float*)d_in[4];
    const float* g0     = (const float*)d_in[5];
    const float* be0    = (const float*)d_in[6];
    const float* g1     = (const float*)d_in[7];
    const float* be1    = (const float*)d_in[8];
    const float* normal = (const float*)d_in[9];
    const float* Win    = (const float*)d_in[10];
    float* out = (float*)d_out;

    const int smem2 = SM2_FLOATS * 4;  // 108200 bytes
    cudaFuncSetAttribute(k_attn, cudaFuncAttributeMaxDynamicSharedMemorySize, smem2);

    k_proj<<<(BATCH * NN) / 64, 256>>>(x, Wq, bq, Wk, bk, g0, be0, g1, be1);
    k_attn<<<dim3(NN / BM, BATCH), 256, smem2>>>(normal, out);
    k_time<<<(BATCH * NN) / 8, 256>>>(x, Win, out);
}

// round 2
// speedup vs baseline: 1.0071x; 1.0071x over previous
#include <cuda_runtime.h>
#include <math.h>

#define BATCH 32
#define NN    2000
#define TD    384
#define EMB   64

// scratch for layernormed q/k projections: 16.4 MB each
__device__ float g_Q[BATCH * NN * EMB];
__device__ float g_K[BATCH * NN * EMB];

typedef unsigned long long u64;

__device__ __forceinline__ void fma2(u64& d, u64 a, u64 b) {
    asm("fma.rn.f32x2 %0, %1, %2, %0;" : "+l"(d) : "l"(a), "l"(b));
}
__device__ __forceinline__ void add2(u64& d, u64 a) {
    asm("add.rn.f32x2 %0, %0, %1;" : "+l"(d) : "l"(a));
}
__device__ __forceinline__ float lo2(u64 v) {
    float2 f = *reinterpret_cast<float2*>(&v);
    return f.x;
}
__device__ __forceinline__ float hsum2(u64 v) {
    float2 f = *reinterpret_cast<float2*>(&v);
    return f.x + f.y;
}

// ---------------------------------------------------------------------------
// Kernel 1: fused  q = LN(xf@Wq+bq), k = LN(xf@Wk+bk)
// ---------------------------------------------------------------------------
__global__ __launch_bounds__(256) void k_proj(
    const float* __restrict__ x,
    const float* __restrict__ Wq, const float* __restrict__ bq,
    const float* __restrict__ Wk, const float* __restrict__ bk,
    const float* __restrict__ g0, const float* __restrict__ be0,
    const float* __restrict__ g1, const float* __restrict__ be1)
{
    __shared__ float xs[64][33];
    __shared__ float ws[32][128];

    const int tid = threadIdx.x;
    const int rg  = tid >> 4;
    const int og  = tid & 15;
    const long R0 = (long)blockIdx.x * 64;

    float acc[4][8];
#pragma unroll
    for (int i = 0; i < 4; i++)
#pragma unroll
        for (int j = 0; j < 8; j++) acc[i][j] = 0.f;

    for (int ch = 0; ch < 12; ch++) {
#pragma unroll
        for (int p = 0; p < 8; p++) {
            int row = (tid >> 5) + 8 * p;
            int c   = tid & 31;
            xs[row][c] = x[(R0 + row) * 384 + ch * 32 + c];
        }
#pragma unroll
        for (int p = 0; p < 16; p++) {
            int idx = tid + 256 * p;
            int e = idx >> 7, o = idx & 127;
            float v = (o < 64) ? Wq[(ch * 32 + e) * 64 + o]
                               : Wk[(ch * 32 + e) * 64 + (o - 64)];
            ws[e][o] = v;
        }
        __syncthreads();

#pragma unroll 4
        for (int e = 0; e < 32; e++) {
            float xv[4];
#pragma unroll
            for (int i = 0; i < 4; i++) xv[i] = xs[rg * 4 + i][e];
#pragma unroll
            for (int j = 0; j < 8; j++) {
                float wv = ws[e][og + 16 * j];
#pragma unroll
                for (int i = 0; i < 4; i++) acc[i][j] += xv[i] * wv;
            }
        }
        __syncthreads();
    }

#pragma unroll
    for (int i = 0; i < 4; i++) {
        int row = rg * 4 + i;
        float vq[4], vk[4];
#pragma unroll
        for (int j = 0; j < 4; j++) {
            int o = og + 16 * j;
            vq[j] = acc[i][j]     + bq[o];
            vk[j] = acc[i][4 + j] + bk[o];
        }
        float qs = 0.f, qs2 = 0.f, ks = 0.f, ks2 = 0.f;
#pragma unroll
        for (int j = 0; j < 4; j++) {
            qs += vq[j]; qs2 += vq[j] * vq[j];
            ks += vk[j]; ks2 += vk[j] * vk[j];
        }
#pragma unroll
        for (int m = 8; m >= 1; m >>= 1) {
            qs  += __shfl_xor_sync(0xffffffffu, qs,  m, 16);
            qs2 += __shfl_xor_sync(0xffffffffu, qs2, m, 16);
            ks  += __shfl_xor_sync(0xffffffffu, ks,  m, 16);
            ks2 += __shfl_xor_sync(0xffffffffu, ks2, m, 16);
        }
        float mq = qs * (1.f / 64.f);
        float rq = rsqrtf(qs2 * (1.f / 64.f) - mq * mq + 1e-5f);
        float mk = ks * (1.f / 64.f);
        float rk = rsqrtf(ks2 * (1.f / 64.f) - mk * mk + 1e-5f);
        long base = (R0 + row) * 64;
#pragma unroll
        for (int j = 0; j < 4; j++) {
            int o = og + 16 * j;
            g_Q[base + o] = (vq[j] - mq) * rq * g0[o] + be0[o];
            g_K[base + o] = (vk[j] - mk) * rk * g1[o] + be1[o];
        }
    }
}

// ---------------------------------------------------------------------------
// Kernel 2: data = softmax(q kT / sqrt(NN)) @ normal
// |score| <= 64/sqrt(2000) = 1.43 -> streaming exp-accumulate (no max sub).
// All hot FMAs are packed fma.rn.f32x2 (FFMA2, 2x fp32 throughput).
// grid (50 n-tiles of 40 rows, 32 batches), block 256, occ 2.
// Accumulator: 40 rows x 192 col-pairs fp32x2 (warp w rows w*5..+4, lane owns
// col pairs 2*lane + 64*jj, jj<6). P stored DUPLICATED {p,p} in smem so the
// PV multiplier is a single broadcast LDS.64.
// ---------------------------------------------------------------------------
#define BM 40
#define BK 40
#define QS_STRIDE 66
#define PS_STRIDE (2 * BK)
#define SM2_FLOATS (BK * 384 + BM * QS_STRIDE + BK * QS_STRIDE + BM * PS_STRIDE)

__global__ __launch_bounds__(256, 2) void k_attn(
    const float* __restrict__ normal, float* __restrict__ out)
{
    extern __shared__ float sm[];
    float* Vs  = sm;                                  // [40][384]
    float* Qs  = sm + BK * 384;                       // [40][66]
    float* Ks  = Qs + BM * QS_STRIDE;                 // [40][66]
    float* Ps2 = Ks + BK * QS_STRIDE;                 // [40][80] duplicated pairs

    const int tid  = threadIdx.x;
    const int wid  = tid >> 5;
    const int lane = tid & 31;
    const int b    = blockIdx.y;
    const int n0   = blockIdx.x * BM;
    const long qbase = (long)b * NN + n0;
    const float SCALE = 0.02236067977f;               // 1/sqrt(2000)

    // load Q tile (40 x 64) into stride-66 smem
    for (int idx = tid; idx < BM * 64; idx += 256) {
        int r = idx >> 6, e = idx & 63;
        Qs[r * QS_STRIDE + e] = g_Q[(qbase + r) * 64 + e];
    }

    u64 acc[5][6];
#pragma unroll
    for (int i = 0; i < 5; i++)
#pragma unroll
        for (int j = 0; j < 6; j++) acc[i][j] = 0ull;
    u64 sums2[5] = {0ull, 0ull, 0ull, 0ull, 0ull};

    const int r0 = wid * 5;
    // S-phase mapping: 200 threads, each 2 rows x 4 cols
    const int rp = tid / 10;      // 0..19 (tid<200) -> rows 2rp, 2rp+1
    const int mg = tid % 10;      // cols 4mg..4mg+3

    for (int mt = 0; mt < NN / BK; mt++) {
        const int m0 = mt * BK;
        __syncthreads();
        // K tile (40 x 64)
        {
            const long kbase = (long)b * NN + m0;
            for (int idx = tid; idx < BK * 64; idx += 256) {
                int r = idx >> 6, e = idx & 63;
                Ks[r * QS_STRIDE + e] = g_K[(kbase + r) * 64 + e];
            }
        }
        // V tile = normal rows m0..m0+39 (40 x 384), flat float4 copy
        {
            const float4* np = (const float4*)(normal + (long)m0 * 384);
            float4* vp = (float4*)Vs;
            for (int idx = tid; idx < BK * 96; idx += 256) vp[idx] = np[idx];
        }
        __syncthreads();

        // S = exp(Q K^T * SCALE), packed-pair dot products over e
        if (tid < 200) {
            u64 s[2][4];
#pragma unroll
            for (int i = 0; i < 2; i++)
#pragma unroll
                for (int j = 0; j < 4; j++) s[i][j] = 0ull;
            const float* q0p = &Qs[(2 * rp) * QS_STRIDE];
            const float* q1p = q0p + QS_STRIDE;
            const float* kp0 = &Ks[(4 * mg) * QS_STRIDE];
#pragma unroll 8
            for (int ep = 0; ep < 32; ep++) {
                u64 q0 = *(const u64*)(q0p + 2 * ep);
                u64 q1 = *(const u64*)(q1p + 2 * ep);
#pragma unroll
                for (int j = 0; j < 4; j++) {
                    u64 kv = *(const u64*)(kp0 + j * QS_STRIDE + 2 * ep);
                    fma2(s[0][j], q0, kv);
                    fma2(s[1][j], q1, kv);
                }
            }
#pragma unroll
            for (int i = 0; i < 2; i++)
#pragma unroll
                for (int j = 0; j < 4; j++) {
                    float p = __expf(hsum2(s[i][j]) * SCALE);
                    *(float2*)&Ps2[(2 * rp + i) * PS_STRIDE + 2 * (4 * mg + j)]
                        = make_float2(p, p);
                }
        }
        __syncthreads();

        // PV accumulate: acc += P @ V (packed), sums += row-sums(P)
#pragma unroll 2
        for (int k = 0; k < BK; k++) {
            u64 pv[5];
#pragma unroll
            for (int i = 0; i < 5; i++) {
                pv[i] = *(const u64*)&Ps2[(r0 + i) * PS_STRIDE + 2 * k];
                add2(sums2[i], pv[i]);
            }
            u64 vv[6];
            const float* vrow = Vs + k * 384 + 2 * lane;
#pragma unroll
            for (int jj = 0; jj < 6; jj++) vv[jj] = *(const u64*)(vrow + 64 * jj);
#pragma unroll
            for (int i = 0; i < 5; i++)
#pragma unroll
                for (int jj = 0; jj < 6; jj++) fma2(acc[i][jj], pv[i], vv[jj]);
        }
    }

    // epilogue: data = acc / rowsum  (both packed halves hold the same sum)
#pragma unroll
    for (int i = 0; i < 5; i++) {
        float inv = 1.f / lo2(sums2[i]);
        size_t base = (size_t)(qbase + r0 + i) * 384 + 2 * lane;
#pragma unroll
        for (int jj = 0; jj < 6; jj++) {
            float2 a = *reinterpret_cast<float2*>(&acc[i][jj]);
            *(float2*)&out[base + 64 * jj] = make_float2(a.x * inv, a.y * inv);
        }
    }
}

// ---------------------------------------------------------------------------
// Kernel 3: time-attention weight + broadcast add (in place on out).
// ---------------------------------------------------------------------------
__global__ __launch_bounds__(256) void k_time(
    const float* __restrict__ x, const float* __restrict__ Win,
    float* __restrict__ out)
{
    const int wid = threadIdx.x >> 5, lane = threadIdx.x & 31;
    const long node = (long)blockIdx.x * 8 + wid;
    __shared__ float qs[8][17];

    const float* xl = x + node * 384 + 368;
    float* dat = out + node * 384;

    if (lane < 16) {
        float q = 0.f;
#pragma unroll
        for (int d = 0; d < 16; d++) q += xl[d] * Win[d * 16 + lane];
        qs[wid][lane] = q;
    }
    __syncwarp();

    float att = -1e30f;
    if (lane < 24) {
        float a = 0.f;
#pragma unroll
        for (int d = 0; d < 16; d++) a += qs[wid][d] * dat[lane * 16 + d];
        att = a;
    }
    float mx = att;
#pragma unroll
    for (int m = 16; m >= 1; m >>= 1)
        mx = fmaxf(mx, __shfl_xor_sync(0xffffffffu, mx, m));
    float e = (lane < 24) ? __expf(att - mx) : 0.f;
    float s = e;
#pragma unroll
    for (int m = 16; m >= 1; m >>= 1)
        s += __shfl_xor_sync(0xffffffffu, s, m);
    float w = e / s;

#pragma unroll
    for (int jj = 0; jj < 12; jj++) {
        int i = lane + 32 * jj;
        int t = i >> 4;
        float wt = __shfl_sync(0xffffffffu, w, t);
        dat[i] += wt;
    }
}

// ---------------------------------------------------------------------------
extern "C" void kernel_launch(void* const* d_in, const int* in_sizes, int n_in,
                              void* d_out, int out_size)
{
    const float* x      = (const float*)d_in[0];
    const float* Wq     = (const float*)d_in[1];
    const float* bq     = (const float*)d_in[2];
    const float* Wk     = (const float*)d_in[3];
    const float* bk     = (const float*)d_in[4];
    const float* g0     = (const float*)d_in[5];
    const float* be0    = (const float*)d_in[6];
    const float* g1     = (const float*)d_in[7];
    const float* be1    = (const float*)d_in[8];
    const float* normal = (const float*)d_in[9];
    const float* Win    = (const float*)d_in[10];
    float* out = (float*)d_out;

    const int smem2 = SM2_FLOATS * 4;   // 95360 bytes
    cudaFuncSetAttribute(k_attn, cudaFuncAttributeMaxDynamicSharedMemorySize, smem2);

    k_proj<<<(BATCH * NN) / 64, 256>>>(x, Wq, bq, Wk, bk, g0, be0, g1, be1);
    k_attn<<<dim3(NN / BM, BATCH), 256, smem2>>>(normal, out);
    k_time<<<(BATCH * NN) / 8, 256>>>(x, Win, out);
}

// round 6
// speedup vs baseline: 1.5170x; 1.5062x over previous
#include <cuda_runtime.h>
#include <cstdint>
#include <math.h>

#define BATCH 32
#define NN    2000
#define EMB   64

// scratch
__device__ float g_Q[BATCH * NN * EMB];   // layernormed q (tf32-rounded)
__device__ float g_K[BATCH * NN * EMB];   // layernormed k (tf32-rounded)
__device__ float g_Vr[2048 * 384];        // normal, tf32-rounded, rows>=2000 zero

// ===========================================================================
// helpers
// ===========================================================================
__device__ __forceinline__ uint32_t smem_u32(const void* p) {
    uint32_t a;
    asm("{ .reg .u64 t; cvta.to.shared.u64 t, %1; cvt.u32.u64 %0, t; }" : "=r"(a) : "l"(p));
    return a;
}
__device__ __forceinline__ void cp_async16(uint32_t dst, const void* src, bool pred) {
    int sz = pred ? 16 : 0;
    asm volatile("cp.async.cg.shared.global [%0], [%1], 16, %2;\n"
                 :: "r"(dst), "l"(src), "r"(sz));
}
__device__ __forceinline__ void cp_commit() { asm volatile("cp.async.commit_group;"); }
__device__ __forceinline__ void cp_wait0()  { asm volatile("cp.async.wait_group 0;" ::: "memory"); }

__device__ __forceinline__ uint32_t to_tf32(float f) {
    uint32_t r;
    asm("cvt.rna.tf32.f32 %0, %1;" : "=r"(r) : "f"(f));
    return r;
}
__device__ __forceinline__ float to_tf32f(float f) {
    return __uint_as_float(to_tf32(f));
}

// D += A(16x8,row) * B(8x8,col)   tf32
__device__ __forceinline__ void mma16n8k8(float* d,
    uint32_t a0, uint32_t a1, uint32_t a2, uint32_t a3,
    uint32_t b0, uint32_t b1)
{
    asm volatile("mma.sync.aligned.m16n8k8.row.col.f32.tf32.tf32.f32 "
        "{%0,%1,%2,%3}, {%4,%5,%6,%7}, {%8,%9}, {%0,%1,%2,%3};"
        : "+f"(d[0]), "+f"(d[1]), "+f"(d[2]), "+f"(d[3])
        : "r"(a0), "r"(a1), "r"(a2), "r"(a3), "r"(b0), "r"(b1));
}

// ===========================================================================
// Kernel 1: fused  q = LN(xf@Wq+bq), k = LN(xf@Wk+bk); outputs tf32-rounded
// ===========================================================================
__global__ __launch_bounds__(256) void k_proj(
    const float* __restrict__ x,
    const float* __restrict__ Wq, const float* __restrict__ bq,
    const float* __restrict__ Wk, const float* __restrict__ bk,
    const float* __restrict__ g0, const float* __restrict__ be0,
    const float* __restrict__ g1, const float* __restrict__ be1)
{
    __shared__ float xs[64][33];
    __shared__ float ws[32][128];

    const int tid = threadIdx.x;
    const int rg  = tid >> 4;
    const int og  = tid & 15;
    const long R0 = (long)blockIdx.x * 64;

    float acc[4][8];
#pragma unroll
    for (int i = 0; i < 4; i++)
#pragma unroll
        for (int j = 0; j < 8; j++) acc[i][j] = 0.f;

    for (int ch = 0; ch < 12; ch++) {
#pragma unroll
        for (int p = 0; p < 8; p++) {
            int row = (tid >> 5) + 8 * p;
            int c   = tid & 31;
            xs[row][c] = x[(R0 + row) * 384 + ch * 32 + c];
        }
#pragma unroll
        for (int p = 0; p < 16; p++) {
            int idx = tid + 256 * p;
            int e = idx >> 7, o = idx & 127;
            float v = (o < 64) ? Wq[(ch * 32 + e) * 64 + o]
                               : Wk[(ch * 32 + e) * 64 + (o - 64)];
            ws[e][o] = v;
        }
        __syncthreads();
#pragma unroll 4
        for (int e = 0; e < 32; e++) {
            float xv[4];
#pragma unroll
            for (int i = 0; i < 4; i++) xv[i] = xs[rg * 4 + i][e];
#pragma unroll
            for (int j = 0; j < 8; j++) {
                float wv = ws[e][og + 16 * j];
#pragma unroll
                for (int i = 0; i < 4; i++) acc[i][j] += xv[i] * wv;
            }
        }
        __syncthreads();
    }

#pragma unroll
    for (int i = 0; i < 4; i++) {
        int row = rg * 4 + i;
        float vq[4], vk[4];
#pragma unroll
        for (int j = 0; j < 4; j++) {
            int o = og + 16 * j;
            vq[j] = acc[i][j]     + bq[o];
            vk[j] = acc[i][4 + j] + bk[o];
        }
        float qs = 0.f, qs2 = 0.f, ks = 0.f, ks2 = 0.f;
#pragma unroll
        for (int j = 0; j < 4; j++) {
            qs += vq[j]; qs2 += vq[j] * vq[j];
            ks += vk[j]; ks2 += vk[j] * vk[j];
        }
#pragma unroll
        for (int m = 8; m >= 1; m >>= 1) {
            qs  += __shfl_xor_sync(0xffffffffu, qs,  m, 16);
            qs2 += __shfl_xor_sync(0xffffffffu, qs2, m, 16);
            ks  += __shfl_xor_sync(0xffffffffu, ks,  m, 16);
            ks2 += __shfl_xor_sync(0xffffffffu, ks2, m, 16);
        }
        float mq = qs * (1.f / 64.f);
        float rq = rsqrtf(qs2 * (1.f / 64.f) - mq * mq + 1e-5f);
        float mk = ks * (1.f / 64.f);
        float rk = rsqrtf(ks2 * (1.f / 64.f) - mk * mk + 1e-5f);
        long base = (R0 + row) * 64;
#pragma unroll
        for (int j = 0; j < 4; j++) {
            int o = og + 16 * j;
            g_Q[base + o] = to_tf32f((vq[j] - mq) * rq * g0[o] + be0[o]);
            g_K[base + o] = to_tf32f((vk[j] - mk) * rk * g1[o] + be1[o]);
        }
    }
}

// ===========================================================================
// Kernel 1b: tf32-round normal into g_Vr (rows >= 2000 zeroed)
// ===========================================================================
__global__ __launch_bounds__(256) void k_cvt(const float* __restrict__ normal)
{
    // 2048*384/4 = 196608 float4; 768 blocks x 256 threads
    const int idx = blockIdx.x * 256 + threadIdx.x;
    const int row = idx / 96;          // 96 quads per row
    float4 v = make_float4(0.f, 0.f, 0.f, 0.f);
    if (row < NN) {
        float4 s = *(const float4*)(normal + (size_t)idx * 4);
        v = make_float4(to_tf32f(s.x), to_tf32f(s.y), to_tf32f(s.z), to_tf32f(s.w));
    }
    *(float4*)(g_Vr + (size_t)idx * 4) = v;
}

// ===========================================================================
// Kernel 2: flash node-attention with mma.sync tf32.
// grid (16 m-tiles of 128 rows, 3 col-slices of 128, 32 batches), 256 thr.
// ===========================================================================
#define CHK    32            // keys per chunk
#define NCHUNK 63            // 63*32 = 2016 >= 2000
#define QSTR   68            // Q/K smem stride
#define VSTR   132           // V smem stride
#define PSTR   36            // P smem stride

#define QS_F  0
#define KS_F  (128 * QSTR)                 // 8704
#define VS_F  (KS_F + 2 * CHK * QSTR)      // 13056
#define PS_F  (VS_F + 2 * CHK * VSTR)      // 21504
#define SMF   (PS_F + 128 * PSTR)          // 26112 floats
#define SMEM_SZ (SMF * 4)                  // 104448 bytes

__global__ __launch_bounds__(256, 2) void k_attn_mma(float* __restrict__ out)
{
    extern __shared__ float sm[];
    const uint32_t sb = smem_u32(sm);
    const int tid  = threadIdx.x;
    const int w    = tid >> 5;
    const int lane = tid & 31;
    const int g    = lane >> 2;          // group row
    const int c    = lane & 3;           // thread in group
    const int mt = blockIdx.x, ns = blockIdx.y, b = blockIdx.z;
    const int n0 = mt * 128;
    const int mr = w * 16;               // warp's row base within tile
    const float SCALE = 0.02236067977f;  // 1/sqrt(2000)

    const long qrow0 = (long)b * NN;

    // ---- initial loads: Q tile + chunk 0 K/V ----
#pragma unroll
    for (int p = 0; p < 8; p++) {                  // Q: 2048 quads
        int idx = tid + 256 * p;
        int row = idx >> 4, q = idx & 15;
        cp_async16(sb + (QS_F + row * QSTR + q * 4) * 4,
                   &g_Q[(qrow0 + n0 + row) * 64 + q * 4], (n0 + row) < NN);
    }
#pragma unroll
    for (int p = 0; p < 2; p++) {                  // K chunk0: 512 quads
        int idx = tid + 256 * p;
        int row = idx >> 4, q = idx & 15;
        cp_async16(sb + (KS_F + row * QSTR + q * 4) * 4,
                   &g_K[(qrow0 + row) * 64 + q * 4], row < NN);
    }
#pragma unroll
    for (int p = 0; p < 4; p++) {                  // V chunk0: 1024 quads
        int idx = tid + 256 * p;
        int row = idx >> 5, q = idx & 31;
        cp_async16(sb + (VS_F + row * VSTR + q * 4) * 4,
                   &g_Vr[(size_t)row * 384 + ns * 128 + q * 4], true);
    }
    cp_commit();

    float d[16][4];
#pragma unroll
    for (int t = 0; t < 16; t++)
#pragma unroll
        for (int j = 0; j < 4; j++) d[t][j] = 0.f;
    float rs0 = 0.f, rs1 = 0.f;

    for (int i = 0; i < NCHUNK; i++) {
        const int buf = i & 1;
        cp_wait0();
        __syncthreads();

        // prefetch chunk i+1
        if (i + 1 < NCHUNK) {
            const int nb = 1 - buf;
            const int k0 = (i + 1) * CHK;
#pragma unroll
            for (int p = 0; p < 2; p++) {
                int idx = tid + 256 * p;
                int row = idx >> 4, q = idx & 15;
                cp_async16(sb + (KS_F + nb * CHK * QSTR + row * QSTR + q * 4) * 4,
                           &g_K[(qrow0 + k0 + row) * 64 + q * 4], (k0 + row) < NN);
            }
#pragma unroll
            for (int p = 0; p < 4; p++) {
                int idx = tid + 256 * p;
                int row = idx >> 5, q = idx & 31;
                cp_async16(sb + (VS_F + nb * CHK * VSTR + row * VSTR + q * 4) * 4,
                           &g_Vr[(size_t)(k0 + row) * 384 + ns * 128 + q * 4], true);
            }
            cp_commit();
        }

        // ---- mma1: S = Q K^T  (16 rows x 32 keys per warp) ----
        const float* Ks = sm + KS_F + buf * CHK * QSTR;
        float s[4][4];
#pragma unroll
        for (int t = 0; t < 4; t++)
#pragma unroll
            for (int j = 0; j < 4; j++) s[t][j] = 0.f;

#pragma unroll
        for (int ks = 0; ks < 8; ks++) {
            uint32_t a0 = __float_as_uint(sm[QS_F + (mr + g)     * QSTR + ks * 8 + c]);
            uint32_t a1 = __float_as_uint(sm[QS_F + (mr + g + 8) * QSTR + ks * 8 + c]);
            uint32_t a2 = __float_as_uint(sm[QS_F + (mr + g)     * QSTR + ks * 8 + c + 4]);
            uint32_t a3 = __float_as_uint(sm[QS_F + (mr + g + 8) * QSTR + ks * 8 + c + 4]);
#pragma unroll
            for (int nt = 0; nt < 4; nt++) {
                uint32_t b0 = __float_as_uint(Ks[(8 * nt + g) * QSTR + ks * 8 + c]);
                uint32_t b1 = __float_as_uint(Ks[(8 * nt + g) * QSTR + ks * 8 + c + 4]);
                mma16n8k8(s[nt], a0, a1, a2, a3, b0, b1);
            }
        }

        // ---- exp + rowsum + P to smem ----
        const int kglob = i * CHK + 2 * c;
#pragma unroll
        for (int nt = 0; nt < 4; nt++) {
            float p0 = __expf(s[nt][0] * SCALE);
            float p1 = __expf(s[nt][1] * SCALE);
            float p2 = __expf(s[nt][2] * SCALE);
            float p3 = __expf(s[nt][3] * SCALE);
            if (i == NCHUNK - 1) {                 // mask keys >= 2000
                int kc = kglob + 8 * nt;
                if (kc     >= NN) { p0 = 0.f; p2 = 0.f; }
                if (kc + 1 >= NN) { p1 = 0.f; p3 = 0.f; }
            }
            rs0 += p0 + p1;
            rs1 += p2 + p3;
            *(float2*)&sm[PS_F + (mr + g)     * PSTR + 8 * nt + 2 * c] =
                make_float2(to_tf32f(p0), to_tf32f(p1));
            *(float2*)&sm[PS_F + (mr + g + 8) * PSTR + 8 * nt + 2 * c] =
                make_float2(to_tf32f(p2), to_tf32f(p3));
        }
        __syncwarp();

        // ---- mma2: D += P V ----
        const float* Vs = sm + VS_F + buf * CHK * VSTR;
#pragma unroll
        for (int ks = 0; ks < 4; ks++) {
            uint32_t a0 = __float_as_uint(sm[PS_F + (mr + g)     * PSTR + ks * 8 + c]);
            uint32_t a1 = __float_as_uint(sm[PS_F + (mr + g + 8) * PSTR + ks * 8 + c]);
            uint32_t a2 = __float_as_uint(sm[PS_F + (mr + g)     * PSTR + ks * 8 + c + 4]);
            uint32_t a3 = __float_as_uint(sm[PS_F + (mr + g + 8) * PSTR + ks * 8 + c + 4]);
#pragma unroll
            for (int nt = 0; nt < 16; nt++) {
                uint32_t b0 = __float_as_uint(Vs[(ks * 8 + c)     * VSTR + 8 * nt + g]);
                uint32_t b1 = __float_as_uint(Vs[(ks * 8 + c + 4) * VSTR + 8 * nt + g]);
                mma16n8k8(d[nt], a0, a1, a2, a3, b0, b1);
            }
        }
    }

    // ---- epilogue: rowsum reduce over quad, divide, store ----
    rs0 += __shfl_xor_sync(0xffffffffu, rs0, 1);
    rs0 += __shfl_xor_sync(0xffffffffu, rs0, 2);
    rs1 += __shfl_xor_sync(0xffffffffu, rs1, 1);
    rs1 += __shfl_xor_sync(0xffffffffu, rs1, 2);
    const float inv0 = 1.f / rs0, inv1 = 1.f / rs1;

    const int r0 = n0 + mr + g;
    const int r1 = r0 + 8;
    float* o0 = out + (qrow0 + r0) * 384 + ns * 128 + 2 * c;
    float* o1 = out + (qrow0 + r1) * 384 + ns * 128 + 2 * c;
#pragma unroll
    for (int nt = 0; nt < 16; nt++) {
        if (r0 < NN) *(float2*)(o0 + 8 * nt) = make_float2(d[nt][0] * inv0, d[nt][1] * inv0);
        if (r1 < NN) *(float2*)(o1 + 8 * nt) = make_float2(d[nt][2] * inv1, d[nt][3] * inv1);
    }
}

// ===========================================================================
// Kernel 3: time-attention weight + broadcast add (in place on out).
// ===========================================================================
__global__ __launch_bounds__(256) void k_time(
    const float* __restrict__ x, const float* __restrict__ Win,
    float* __restrict__ out)
{
    const int wid = threadIdx.x >> 5, lane = threadIdx.x & 31;
    const long node = (long)blockIdx.x * 8 + wid;
    __shared__ float qs[8][17];

    const float* xl = x + node * 384 + 368;
    float* dat = out + node * 384;

    if (lane < 16) {
        float q = 0.f;
#pragma unroll
        for (int d = 0; d < 16; d++) q += xl[d] * Win[d * 16 + lane];
        qs[wid][lane] = q;
    }
    __syncwarp();

    float att = -1e30f;
    if (lane < 24) {
        float a = 0.f;
#pragma unroll
        for (int d = 0; d < 16; d++) a += qs[wid][d] * dat[lane * 16 + d];
        att = a;
    }
    float mx = att;
#pragma unroll
    for (int m = 16; m >= 1; m >>= 1)
        mx = fmaxf(mx, __shfl_xor_sync(0xffffffffu, mx, m));
    float e = (lane < 24) ? __expf(att - mx) : 0.f;
    float s = e;
#pragma unroll
    for (int m = 16; m >= 1; m >>= 1)
        s += __shfl_xor_sync(0xffffffffu, s, m);
    float wgt = e / s;

#pragma unroll
    for (int jj = 0; jj < 12; jj++) {
        int i = lane + 32 * jj;
        int t = i >> 4;
        float wt = __shfl_sync(0xffffffffu, wgt, t);
        dat[i] += wt;
    }
}

// ===========================================================================
extern "C" void kernel_launch(void* const* d_in, const int* in_sizes, int n_in,
                              void* d_out, int out_size)
{
    const float* x      = (const float*)d_in[0];
    const float* Wq     = (const float*)d_in[1];
    const float* bq     = (const float*)d_in[2];
    const float* Wk     = (const float*)d_in[3];
    const float* bk     = (const float*)d_in[4];
    const float* g0     = (const float*)d_in[5];
    const float* be0    = (const float*)d_in[6];
    const float* g1     = (const float*)d_in[7];
    const float* be1    = (const float*)d_in[8];
    const float* normal = (const float*)d_in[9];
    const float* Win    = (const float*)d_in[10];
    float* out = (float*)d_out;

    cudaFuncSetAttribute(k_attn_mma, cudaFuncAttributeMaxDynamicSharedMemorySize, SMEM_SZ);

    k_proj<<<(BATCH * NN) / 64, 256>>>(x, Wq, bq, Wk, bk, g0, be0, g1, be1);
    k_cvt<<<768, 256>>>(normal);
    k_attn_mma<<<dim3(16, 3, BATCH), 256, SMEM_SZ>>>(out);
    k_time<<<(BATCH * NN) / 8, 256>>>(x, Win, out);
}

// round 8
// speedup vs baseline: 3.5191x; 2.3197x over previous
#include <cuda_runtime.h>
#include <cstdint>
#include <math.h>

#define BATCH 32
#define NN    2000
#define EMB   64

// scratch
__device__ float g_Q[BATCH * NN * EMB];   // LN q, tf32-rounded, e-cols permuted
__device__ float g_K[BATCH * NN * EMB];   // LN k, tf32-rounded, e-cols permuted
__device__ float g_VT[384 * 2048];        // normal^T, tf32-rounded, keys>=2000 zero

// ===========================================================================
// helpers
// ===========================================================================
__device__ __forceinline__ uint32_t smem_u32(const void* p) {
    uint32_t a;
    asm("{ .reg .u64 t; cvta.to.shared.u64 t, %1; cvt.u32.u64 %0, t; }" : "=r"(a) : "l"(p));
    return a;
}
__device__ __forceinline__ void cp_async16(uint32_t dst, const void* src, bool pred) {
    int sz = pred ? 16 : 0;
    asm volatile("cp.async.cg.shared.global [%0], [%1], 16, %2;\n"
                 :: "r"(dst), "l"(src), "r"(sz));
}
__device__ __forceinline__ void cp_commit() { asm volatile("cp.async.commit_group;"); }
__device__ __forceinline__ void cp_wait0()  { asm volatile("cp.async.wait_group 0;" ::: "memory"); }

__device__ __forceinline__ uint32_t to_tf32(float f) {
    uint32_t r;
    asm("cvt.rna.tf32.f32 %0, %1;" : "=r"(r) : "f"(f));
    return r;
}
__device__ __forceinline__ float to_tf32f(float f) {
    return __uint_as_float(to_tf32(f));
}

// D += A(16x8,row) * B(8x8,col)   tf32
__device__ __forceinline__ void mma16n8k8(float* d,
    uint32_t a0, uint32_t a1, uint32_t a2, uint32_t a3,
    uint32_t b0, uint32_t b1)
{
    asm volatile("mma.sync.aligned.m16n8k8.row.col.f32.tf32.tf32.f32 "
        "{%0,%1,%2,%3}, {%4,%5,%6,%7}, {%8,%9}, {%0,%1,%2,%3};"
        : "+f"(d[0]), "+f"(d[1]), "+f"(d[2]), "+f"(d[3])
        : "r"(a0), "r"(a1), "r"(a2), "r"(a3), "r"(b0), "r"(b1));
}

// column permutation within 8-groups: slot j -> position (j<4 ? 2j : 2j-7)
__device__ __forceinline__ int permcol(int o) {
    int j = o & 7;
    return (o & ~7) | ((j < 4) ? (2 * j) : (2 * j - 7));
}

// ===========================================================================
// Kernel 1: fused  q = LN(xf@Wq+bq), k = LN(xf@Wk+bk)
// outputs tf32-rounded, columns stored permuted for fragment-pair loads
// ===========================================================================
__global__ __launch_bounds__(256) void k_proj(
    const float* __restrict__ x,
    const float* __restrict__ Wq, const float* __restrict__ bq,
    const float* __restrict__ Wk, const float* __restrict__ bk,
    const float* __restrict__ g0, const float* __restrict__ be0,
    const float* __restrict__ g1, const float* __restrict__ be1)
{
    __shared__ float xs[64][33];
    __shared__ float ws[32][128];

    const int tid = threadIdx.x;
    const int rg  = tid >> 4;
    const int og  = tid & 15;
    const long R0 = (long)blockIdx.x * 64;

    float acc[4][8];
#pragma unroll
    for (int i = 0; i < 4; i++)
#pragma unroll
        for (int j = 0; j < 8; j++) acc[i][j] = 0.f;

    for (int ch = 0; ch < 12; ch++) {
#pragma unroll
        for (int p = 0; p < 8; p++) {
            int row = (tid >> 5) + 8 * p;
            int c   = tid & 31;
            xs[row][c] = x[(R0 + row) * 384 + ch * 32 + c];
        }
#pragma unroll
        for (int p = 0; p < 16; p++) {
            int idx = tid + 256 * p;
            int e = idx >> 7, o = idx & 127;
            float v = (o < 64) ? Wq[(ch * 32 + e) * 64 + o]
                               : Wk[(ch * 32 + e) * 64 + (o - 64)];
            ws[e][o] = v;
        }
        __syncthreads();
#pragma unroll 4
        for (int e = 0; e < 32; e++) {
            float xv[4];
#pragma unroll
            for (int i = 0; i < 4; i++) xv[i] = xs[rg * 4 + i][e];
#pragma unroll
            for (int j = 0; j < 8; j++) {
                float wv = ws[e][og + 16 * j];
#pragma unroll
                for (int i = 0; i < 4; i++) acc[i][j] += xv[i] * wv;
            }
        }
        __syncthreads();
    }

#pragma unroll
    for (int i = 0; i < 4; i++) {
        int row = rg * 4 + i;
        float vq[4], vk[4];
#pragma unroll
        for (int j = 0; j < 4; j++) {
            int o = og + 16 * j;
            vq[j] = acc[i][j]     + bq[o];
            vk[j] = acc[i][4 + j] + bk[o];
        }
        float qs = 0.f, qs2 = 0.f, ks = 0.f, ks2 = 0.f;
#pragma unroll
        for (int j = 0; j < 4; j++) {
            qs += vq[j]; qs2 += vq[j] * vq[j];
            ks += vk[j]; ks2 += vk[j] * vk[j];
        }
#pragma unroll
        for (int m = 8; m >= 1; m >>= 1) {
            qs  += __shfl_xor_sync(0xffffffffu, qs,  m, 16);
            qs2 += __shfl_xor_sync(0xffffffffu, qs2, m, 16);
            ks  += __shfl_xor_sync(0xffffffffu, ks,  m, 16);
            ks2 += __shfl_xor_sync(0xffffffffu, ks2, m, 16);
        }
        float mq = qs * (1.f / 64.f);
        float rq = rsqrtf(qs2 * (1.f / 64.f) - mq * mq + 1e-5f);
        float mk = ks * (1.f / 64.f);
        float rk = rsqrtf(ks2 * (1.f / 64.f) - mk * mk + 1e-5f);
        long base = (R0 + row) * 64;
#pragma unroll
        for (int j = 0; j < 4; j++) {
            int o = og + 16 * j;
            int pos = permcol(o);
            g_Q[base + pos] = to_tf32f((vq[j] - mq) * rq * g0[o] + be0[o]);
            g_K[base + pos] = to_tf32f((vk[j] - mk) * rk * g1[o] + be1[o]);
        }
    }
}

// ===========================================================================
// Kernel 1b: transpose normal (2000x384) -> g_VT (384x2048), tf32, zero pad
// ===========================================================================
__global__ __launch_bounds__(256) void k_transpose(const float* __restrict__ normal)
{
    __shared__ float t[32][33];
    const int m0 = blockIdx.x * 32;     // key dim, 64 tiles
    const int c0 = blockIdx.y * 32;     // col dim, 12 tiles
    const int tx = threadIdx.x & 31, ty = threadIdx.x >> 5;
#pragma unroll
    for (int p = 0; p < 4; p++) {
        int m = m0 + ty + 8 * p;
        t[ty + 8 * p][tx] = (m < NN) ? to_tf32f(normal[(long)m * 384 + c0 + tx]) : 0.f;
    }
    __syncthreads();
#pragma unroll
    for (int p = 0; p < 4; p++) {
        int c = c0 + ty + 8 * p;
        g_VT[(long)c * 2048 + m0 + tx] = t[tx][ty + 8 * p];
    }
}

// ===========================================================================
// Kernel 2: flash node-attention, mma.sync tf32, fully vectorized fragments.
// grid (16 m-tiles x 3 col-slices x 32 batches), 256 threads, occ 2.
// Q fragments register-resident; P never leaves registers (slot permutation).
// ===========================================================================
#define CHK    32
#define NCHUNK 63            // 63*32 = 2016 >= 2000
#define QSTR   72            // Q/K smem stride (floats)
#define VTSTR  40            // Vt smem stride (floats)

#define QS_F  0                          // 128*72      = 9216
#define KS_F  (128 * QSTR)               // 2*32*72     = 4608
#define VT_F  (KS_F + 2 * CHK * QSTR)    // 2*128*40    = 10240
#define SMF   (VT_F + 2 * 128 * VTSTR)   // 24064 floats
#define SMEM_SZ (SMF * 4)                // 96256 bytes

__global__ __launch_bounds__(256, 2) void k_attn_mma(float* __restrict__ out)
{
    extern __shared__ float sm[];
    const uint32_t sb = smem_u32(sm);
    const int tid  = threadIdx.x;
    const int w    = tid >> 5;
    const int lane = tid & 31;
    const int g    = lane >> 2;
    const int c    = lane & 3;
    const int mt = blockIdx.x, ns = blockIdx.y, b = blockIdx.z;
    const int n0 = mt * 128;
    const int mr = w * 16;
    const float SCALE = 0.02236067977f;  // 1/sqrt(2000)
    const long qrow0 = (long)b * NN;

    // ---- initial loads: Q tile + chunk 0 K/V ----
#pragma unroll
    for (int p = 0; p < 8; p++) {                  // Q: 2048 quads
        int idx = tid + 256 * p;
        int row = idx >> 4, q = idx & 15;
        cp_async16(sb + (QS_F + row * QSTR + q * 4) * 4,
                   &g_Q[(qrow0 + n0 + row) * 64 + q * 4], (n0 + row) < NN);
    }
#pragma unroll
    for (int p = 0; p < 2; p++) {                  // K chunk0: 512 quads
        int idx = tid + 256 * p;
        int row = idx >> 4, q = idx & 15;
        cp_async16(sb + (KS_F + row * QSTR + q * 4) * 4,
                   &g_K[(qrow0 + row) * 64 + q * 4], row < NN);
    }
#pragma unroll
    for (int p = 0; p < 4; p++) {                  // Vt chunk0: 1024 quads
        int idx = tid + 256 * p;
        int n = idx >> 3, q = idx & 7;
        cp_async16(sb + (VT_F + n * VTSTR + q * 4) * 4,
                   &g_VT[(size_t)(ns * 128 + n) * 2048 + q * 4], true);
    }
    cp_commit();
    cp_wait0();
    __syncthreads();

    // ---- Q fragments -> registers (loop invariant) ----
    uint32_t qa[8][4];
    {
        const float2* q0 = (const float2*)(sm + QS_F + (mr + g) * QSTR);
        const float2* q1 = (const float2*)(sm + QS_F + (mr + g + 8) * QSTR);
#pragma unroll
        for (int ks = 0; ks < 8; ks++) {
            float2 x0 = q0[ks * 4 + c];
            float2 x1 = q1[ks * 4 + c];
            qa[ks][0] = __float_as_uint(x0.x);
            qa[ks][1] = __float_as_uint(x1.x);
            qa[ks][2] = __float_as_uint(x0.y);
            qa[ks][3] = __float_as_uint(x1.y);
        }
    }

    float d[16][4];
#pragma unroll
    for (int t = 0; t < 16; t++)
#pragma unroll
        for (int j = 0; j < 4; j++) d[t][j] = 0.f;
    float rs0 = 0.f, rs1 = 0.f;

    for (int i = 0; i < NCHUNK; i++) {
        const int buf = i & 1;

        // prefetch chunk i+1 into the other buffer
        if (i + 1 < NCHUNK) {
            const int nb = 1 - buf;
            const int k0 = (i + 1) * CHK;
#pragma unroll
            for (int p = 0; p < 2; p++) {
                int idx = tid + 256 * p;
                int row = idx >> 4, q = idx & 15;
                cp_async16(sb + (KS_F + nb * CHK * QSTR + row * QSTR + q * 4) * 4,
                           &g_K[(qrow0 + k0 + row) * 64 + q * 4], (k0 + row) < NN);
            }
#pragma unroll
            for (int p = 0; p < 4; p++) {
                int idx = tid + 256 * p;
                int n = idx >> 3, q = idx & 7;
                cp_async16(sb + (VT_F + nb * 128 * VTSTR + n * VTSTR + q * 4) * 4,
                           &g_VT[(size_t)(ns * 128 + n) * 2048 + k0 + q * 4], true);
            }
            cp_commit();
        }

        // ---- mma1: S = Q K^T (16 rows x 32 keys per warp) ----
        const float2* KsF2 = (const float2*)(sm + KS_F + buf * CHK * QSTR);
        float s[4][4];
#pragma unroll
        for (int t = 0; t < 4; t++)
#pragma unroll
            for (int j = 0; j < 4; j++) s[t][j] = 0.f;

#pragma unroll
        for (int ks = 0; ks < 8; ks++) {
#pragma unroll
            for (int nt = 0; nt < 4; nt++) {
                float2 kb = KsF2[(8 * nt + g) * (QSTR / 2) + ks * 4 + c];
                mma16n8k8(s[nt], qa[ks][0], qa[ks][1], qa[ks][2], qa[ks][3],
                          __float_as_uint(kb.x), __float_as_uint(kb.y));
            }
        }

        // ---- fused exp + rowsum + mma2 (P stays in registers) ----
        const float2* VtF2 = (const float2*)(sm + VT_F + buf * 128 * VTSTR);
#pragma unroll
        for (int ks = 0; ks < 4; ks++) {
            float p0 = __expf(s[ks][0] * SCALE);   // row g,   key 8ks+2c
            float p1 = __expf(s[ks][1] * SCALE);   // row g,   key 8ks+2c+1
            float p2 = __expf(s[ks][2] * SCALE);   // row g+8, key 8ks+2c
            float p3 = __expf(s[ks][3] * SCALE);   // row g+8, key 8ks+2c+1
            if (i == NCHUNK - 1) {
                int kc = i * CHK + 8 * ks + 2 * c;
                if (kc     >= NN) { p0 = 0.f; p2 = 0.f; }
                if (kc + 1 >= NN) { p1 = 0.f; p3 = 0.f; }
            }
            rs0 += p0 + p1;
            rs1 += p2 + p3;
            // A-fragment with slot permutation: slot c -> key 2c, c+4 -> 2c+1
            uint32_t a0 = to_tf32(p0), a1 = to_tf32(p2);
            uint32_t a2 = to_tf32(p1), a3 = to_tf32(p3);
#pragma unroll
            for (int nt = 0; nt < 16; nt++) {
                float2 vb = VtF2[(8 * nt + g) * (VTSTR / 2) + ks * 4 + c];
                mma16n8k8(d[nt], a0, a1, a2, a3,
                          __float_as_uint(vb.x), __float_as_uint(vb.y));
            }
        }

        cp_wait0();
        __syncthreads();
    }

    // ---- epilogue ----
    rs0 += __shfl_xor_sync(0xffffffffu, rs0, 1);
    rs0 += __shfl_xor_sync(0xffffffffu, rs0, 2);
    rs1 += __shfl_xor_sync(0xffffffffu, rs1, 1);
    rs1 += __shfl_xor_sync(0xffffffffu, rs1, 2);
    const float inv0 = 1.f / rs0, inv1 = 1.f / rs1;

    const int r0 = n0 + mr + g;
    const int r1 = r0 + 8;
    float* o0 = out + (qrow0 + r0) * 384 + ns * 128 + 2 * c;
    float* o1 = out + (qrow0 + r1) * 384 + ns * 128 + 2 * c;
#pragma unroll
    for (int nt = 0; nt < 16; nt++) {
        if (r0 < NN) *(float2*)(o0 + 8 * nt) = make_float2(d[nt][0] * inv0, d[nt][1] * inv0);
        if (r1 < NN) *(float2*)(o1 + 8 * nt) = make_float2(d[nt][2] * inv1, d[nt][3] * inv1);
    }
}

// ===========================================================================
// Kernel 3: time-attention weight + broadcast add (in place on out).
// ===========================================================================
__global__ __launch_bounds__(256) void k_time(
    const float* __restrict__ x, const float* __restrict__ Win,
    float* __restrict__ out)
{
    const int wid = threadIdx.x >> 5, lane = threadIdx.x & 31;
    const long node = (long)blockIdx.x * 8 + wid;
    __shared__ float qs[8][17];

    const float* xl = x + node * 384 + 368;
    float* dat = out + node * 384;

    if (lane < 16) {
        float q = 0.f;
#pragma unroll
        for (int d = 0; d < 16; d++) q += xl[d] * Win[d * 16 + lane];
        qs[wid][lane] = q;
    }
    __syncwarp();

    float att = -1e30f;
    if (lane < 24) {
        float a = 0.f;
#pragma unroll
        for (int d = 0; d < 16; d++) a += qs[wid][d] * dat[lane * 16 + d];
        att = a;
    }
    float mx = att;
#pragma unroll
    for (int m = 16; m >= 1; m >>= 1)
        mx = fmaxf(mx, __shfl_xor_sync(0xffffffffu, mx, m));
    float e = (lane < 24) ? __expf(att - mx) : 0.f;
    float s = e;
#pragma unroll
    for (int m = 16; m >= 1; m >>= 1)
        s += __shfl_xor_sync(0xffffffffu, s, m);
    float wgt = e / s;

#pragma unroll
    for (int jj = 0; jj < 12; jj++) {
        int i = lane + 32 * jj;
        int t = i >> 4;
        float wt = __shfl_sync(0xffffffffu, wgt, t);
        dat[i] += wt;
    }
}

// ===========================================================================
extern "C" void kernel_launch(void* const* d_in, const int* in_sizes, int n_in,
                              void* d_out, int out_size)
{
    const float* x      = (const float*)d_in[0];
    const float* Wq     = (const float*)d_in[1];
    const float* bq     = (const float*)d_in[2];
    const float* Wk     = (const float*)d_in[3];
    const float* bk     = (const float*)d_in[4];
    const float* g0     = (const float*)d_in[5];
    const float* be0    = (const float*)d_in[6];
    const float* g1     = (const float*)d_in[7];
    const float* be1    = (const float*)d_in[8];
    const float* normal = (const float*)d_in[9];
    const float* Win    = (const float*)d_in[10];
    float* out = (float*)d_out;

    cudaFuncSetAttribute(k_attn_mma, cudaFuncAttributeMaxDynamicSharedMemorySize, SMEM_SZ);

    k_proj<<<(BATCH * NN) / 64, 256>>>(x, Wq, bq, Wk, bk, g0, be0, g1, be1);
    k_transpose<<<dim3(64, 12), 256>>>(normal);
    k_attn_mma<<<dim3(16, 3, BATCH), 256, SMEM_SZ>>>(out);
    k_time<<<(BATCH * NN) / 8, 256>>>(x, Win, out);
}

// round 9
// speedup vs baseline: 3.9391x; 1.1194x over previous
#include <cuda_runtime.h>
#include <cstdint>
#include <math.h>

#define BATCH 32
#define NN    2000
#define EMB   64

// scratch
__device__ float g_Q[BATCH * NN * EMB];   // LN q, tf32-rounded, e-cols permuted
__device__ float g_K[BATCH * NN * EMB];   // LN k, tf32-rounded, e-cols permuted
__device__ float g_VT[384 * 2048];        // normal^T, tf32-rounded, keys>=2000 zero

// ===========================================================================
// helpers
// ===========================================================================
__device__ __forceinline__ uint32_t smem_u32(const void* p) {
    uint32_t a;
    asm("{ .reg .u64 t; cvta.to.shared.u64 t, %1; cvt.u32.u64 %0, t; }" : "=r"(a) : "l"(p));
    return a;
}
__device__ __forceinline__ void cp_async16(uint32_t dst, const void* src, bool pred) {
    int sz = pred ? 16 : 0;
    asm volatile("cp.async.cg.shared.global [%0], [%1], 16, %2;\n"
                 :: "r"(dst), "l"(src), "r"(sz));
}
__device__ __forceinline__ void cp_commit() { asm volatile("cp.async.commit_group;"); }
__device__ __forceinline__ void cp_wait0()  { asm volatile("cp.async.wait_group 0;" ::: "memory"); }

__device__ __forceinline__ uint32_t to_tf32(float f) {
    uint32_t r;
    asm("cvt.rna.tf32.f32 %0, %1;" : "=r"(r) : "f"(f));
    return r;
}
__device__ __forceinline__ float to_tf32f(float f) {
    return __uint_as_float(to_tf32(f));
}

// D += A(16x8,row) * B(8x8,col)   tf32
__device__ __forceinline__ void mma16n8k8(float* d,
    uint32_t a0, uint32_t a1, uint32_t a2, uint32_t a3,
    uint32_t b0, uint32_t b1)
{
    asm volatile("mma.sync.aligned.m16n8k8.row.col.f32.tf32.tf32.f32 "
        "{%0,%1,%2,%3}, {%4,%5,%6,%7}, {%8,%9}, {%0,%1,%2,%3};"
        : "+f"(d[0]), "+f"(d[1]), "+f"(d[2]), "+f"(d[3])
        : "r"(a0), "r"(a1), "r"(a2), "r"(a3), "r"(b0), "r"(b1));
}

// column permutation within 8-groups: slot j -> position (j<4 ? 2j : 2j-7)
__device__ __forceinline__ int permcol(int o) {
    int j = o & 7;
    return (o & ~7) | ((j < 4) ? (2 * j) : (2 * j - 7));
}

// ===========================================================================
// Kernel 1: q = LN(xf@Wq+bq), k = LN(xf@Wk+bk) on tensor cores.
// CTA = 64 rows x 128 outs (q|k). K=384 in 4 double-buffered chunks of 96.
// 8 warps: warp (rw = w&3, ow = w>>2) owns rows rw*16..+15, outs ow*64..+63.
// W staged UNtransposed [k][out] (row.col B-frag = W[k][n] directly).
// Outputs tf32-rounded, e-cols permuted (matches k_attn fragment loads).
// ===========================================================================
#define KP_XSTR 100
#define KP_WSTR 132
#define KP_XS   0                          // 2 * 64*100  = 12800
#define KP_WS   12800                      // 2 * 96*132  = 25344
#define KP_PB   38144
#define KP_PG   38272
#define KP_PBE  38400
#define KP_SMF  38528
#define KP_SMEM (KP_SMF * 4)               // 154112 bytes

__global__ __launch_bounds__(256, 1) void k_proj_mma(
    const float* __restrict__ x,
    const float* __restrict__ Wq, const float* __restrict__ bq,
    const float* __restrict__ Wk, const float* __restrict__ bk,
    const float* __restrict__ g0, const float* __restrict__ be0,
    const float* __restrict__ g1, const float* __restrict__ be1)
{
    extern __shared__ float sp[];
    const uint32_t sb = smem_u32(sp);
    const int tid  = threadIdx.x;
    const int w    = tid >> 5;
    const int lane = tid & 31;
    const int g    = lane >> 2;
    const int c    = lane & 3;
    const int rw   = w & 3,  ow = w >> 2;
    const int rbase = rw * 16;
    const int n0    = ow * 64;
    const long R0 = (long)blockIdx.x * 64;

    // stage LN params
    if (tid < 128) {
        int o = tid;
        sp[KP_PB  + o] = (o < 64) ? bq[o]  : bk[o - 64];
        sp[KP_PG  + o] = (o < 64) ? g0[o]  : g1[o - 64];
        sp[KP_PBE + o] = (o < 64) ? be0[o] : be1[o - 64];
    }

    // preload chunk 0
#pragma unroll
    for (int p = 0; p < 6; p++) {              // x: 64 rows x 24 quads
        int idx = tid + 256 * p;
        int row = idx / 24, qd = idx % 24;
        cp_async16(sb + (KP_XS + row * KP_XSTR + qd * 4) * 4,
                   &x[(R0 + row) * 384 + qd * 4], true);
    }
#pragma unroll
    for (int p = 0; p < 12; p++) {             // W: 96 k-rows x 32 quads
        int idx = tid + 256 * p;
        int k = idx >> 5, qd = idx & 31;
        const float* src = (qd < 16) ? &Wq[(size_t)k * 64 + qd * 4]
                                     : &Wk[(size_t)k * 64 + (qd - 16) * 4];
        cp_async16(sb + (KP_WS + k * KP_WSTR + qd * 4) * 4, src, true);
    }
    cp_commit();

    float d[8][4];
#pragma unroll
    for (int t = 0; t < 8; t++)
#pragma unroll
        for (int j = 0; j < 4; j++) d[t][j] = 0.f;

    for (int ch = 0; ch < 4; ch++) {
        cp_wait0();
        __syncthreads();

        if (ch < 3) {
            const int nb = (ch + 1) & 1;
            const int kc = (ch + 1) * 96;
#pragma unroll
            for (int p = 0; p < 6; p++) {
                int idx = tid + 256 * p;
                int row = idx / 24, qd = idx % 24;
                cp_async16(sb + (KP_XS + nb * 6400 + row * KP_XSTR + qd * 4) * 4,
                           &x[(R0 + row) * 384 + kc + qd * 4], true);
            }
#pragma unroll
            for (int p = 0; p < 12; p++) {
                int idx = tid + 256 * p;
                int k = idx >> 5, qd = idx & 31;
                const float* src = (qd < 16) ? &Wq[(size_t)(kc + k) * 64 + qd * 4]
                                             : &Wk[(size_t)(kc + k) * 64 + (qd - 16) * 4];
                cp_async16(sb + (KP_WS + nb * 12672 + k * KP_WSTR + qd * 4) * 4, src, true);
            }
            cp_commit();
        }

        const float* xs = sp + KP_XS + (ch & 1) * 6400;
        const float* ws = sp + KP_WS + (ch & 1) * 12672;

#pragma unroll
        for (int ks = 0; ks < 12; ks++) {
            const int kk = ks * 8;
            uint32_t a0 = to_tf32(xs[(rbase + g)     * KP_XSTR + kk + c]);
            uint32_t a1 = to_tf32(xs[(rbase + g + 8) * KP_XSTR + kk + c]);
            uint32_t a2 = to_tf32(xs[(rbase + g)     * KP_XSTR + kk + c + 4]);
            uint32_t a3 = to_tf32(xs[(rbase + g + 8) * KP_XSTR + kk + c + 4]);
#pragma unroll
            for (int nt = 0; nt < 8; nt++) {
                uint32_t b0 = to_tf32(ws[(kk + c)     * KP_WSTR + n0 + nt * 8 + g]);
                uint32_t b1 = to_tf32(ws[(kk + c + 4) * KP_WSTR + n0 + nt * 8 + g]);
                mma16n8k8(d[nt], a0, a1, a2, a3, b0, b1);
            }
        }
    }

    // ---- epilogue: bias + LN (quad-reduced) + permuted tf32 store ----
    float v[8][4];
    float s0 = 0.f, q0 = 0.f, s1 = 0.f, q1 = 0.f;
#pragma unroll
    for (int nt = 0; nt < 8; nt++)
#pragma unroll
        for (int j = 0; j < 4; j++) {
            int col = n0 + nt * 8 + 2 * c + (j & 1);
            float t = d[nt][j] + sp[KP_PB + col];
            v[nt][j] = t;
            if (j < 2) { s0 += t; q0 += t * t; }
            else       { s1 += t; q1 += t * t; }
        }
#pragma unroll
    for (int m = 1; m <= 2; m <<= 1) {
        s0 += __shfl_xor_sync(0xffffffffu, s0, m);
        q0 += __shfl_xor_sync(0xffffffffu, q0, m);
        s1 += __shfl_xor_sync(0xffffffffu, s1, m);
        q1 += __shfl_xor_sync(0xffffffffu, q1, m);
    }
    const float mu0 = s0 * (1.f / 64.f);
    const float r0v = rsqrtf(q0 * (1.f / 64.f) - mu0 * mu0 + 1e-5f);
    const float mu1 = s1 * (1.f / 64.f);
    const float r1v = rsqrtf(q1 * (1.f / 64.f) - mu1 * mu1 + 1e-5f);

    float* dst = ow ? g_K : g_Q;
    const long base0 = (R0 + rbase + g) * 64;
    const long base1 = base0 + 8 * 64;
#pragma unroll
    for (int nt = 0; nt < 8; nt++)
#pragma unroll
        for (int par = 0; par < 2; par++) {
            int o   = nt * 8 + 2 * c + par;
            int col = n0 + o;
            int pos = permcol(o);
            float gv = sp[KP_PG + col], bev = sp[KP_PBE + col];
            dst[base0 + pos] = to_tf32f((v[nt][par]     - mu0) * r0v * gv + bev);
            dst[base1 + pos] = to_tf32f((v[nt][2 + par] - mu1) * r1v * gv + bev);
        }
}

// ===========================================================================
// Kernel 1b: transpose normal (2000x384) -> g_VT (384x2048), tf32, zero pad
// ===========================================================================
__global__ __launch_bounds__(256) void k_transpose(const float* __restrict__ normal)
{
    __shared__ float t[32][33];
    const int m0 = blockIdx.x * 32;
    const int c0 = blockIdx.y * 32;
    const int tx = threadIdx.x & 31, ty = threadIdx.x >> 5;
#pragma unroll
    for (int p = 0; p < 4; p++) {
        int m = m0 + ty + 8 * p;
        t[ty + 8 * p][tx] = (m < NN) ? to_tf32f(normal[(long)m * 384 + c0 + tx]) : 0.f;
    }
    __syncthreads();
#pragma unroll
    for (int p = 0; p < 4; p++) {
        int c = c0 + ty + 8 * p;
        g_VT[(long)c * 2048 + m0 + tx] = t[tx][ty + 8 * p];
    }
}

// ===========================================================================
// Kernel 2: flash node-attention, mma.sync tf32 (unchanged from R8 winner)
// ===========================================================================
#define CHK    32
#define NCHUNK 63
#define QSTR   72
#define VTSTR  40

#define QS_F  0
#define KS_F  (128 * QSTR)
#define VT_F  (KS_F + 2 * CHK * QSTR)
#define SMF   (VT_F + 2 * 128 * VTSTR)
#define SMEM_SZ (SMF * 4)

__global__ __launch_bounds__(256, 2) void k_attn_mma(float* __restrict__ out)
{
    extern __shared__ float sm[];
    const uint32_t sb = smem_u32(sm);
    const int tid  = threadIdx.x;
    const int w    = tid >> 5;
    const int lane = tid & 31;
    const int g    = lane >> 2;
    const int c    = lane & 3;
    const int mt = blockIdx.x, ns = blockIdx.y, b = blockIdx.z;
    const int n0 = mt * 128;
    const int mr = w * 16;
    const float SCALE = 0.02236067977f;
    const long qrow0 = (long)b * NN;

#pragma unroll
    for (int p = 0; p < 8; p++) {
        int idx = tid + 256 * p;
        int row = idx >> 4, q = idx & 15;
        cp_async16(sb + (QS_F + row * QSTR + q * 4) * 4,
                   &g_Q[(qrow0 + n0 + row) * 64 + q * 4], (n0 + row) < NN);
    }
#pragma unroll
    for (int p = 0; p < 2; p++) {
        int idx = tid + 256 * p;
        int row = idx >> 4, q = idx & 15;
        cp_async16(sb + (KS_F + row * QSTR + q * 4) * 4,
                   &g_K[(qrow0 + row) * 64 + q * 4], row < NN);
    }
#pragma unroll
    for (int p = 0; p < 4; p++) {
        int idx = tid + 256 * p;
        int n = idx >> 3, q = idx & 7;
        cp_async16(sb + (VT_F + n * VTSTR + q * 4) * 4,
                   &g_VT[(size_t)(ns * 128 + n) * 2048 + q * 4], true);
    }
    cp_commit();
    cp_wait0();
    __syncthreads();

    uint32_t qa[8][4];
    {
        const float2* q0 = (const float2*)(sm + QS_F + (mr + g) * QSTR);
        const float2* q1 = (const float2*)(sm + QS_F + (mr + g + 8) * QSTR);
#pragma unroll
        for (int ks = 0; ks < 8; ks++) {
            float2 x0 = q0[ks * 4 + c];
            float2 x1 = q1[ks * 4 + c];
            qa[ks][0] = __float_as_uint(x0.x);
            qa[ks][1] = __float_as_uint(x1.x);
            qa[ks][2] = __float_as_uint(x0.y);
            qa[ks][3] = __float_as_uint(x1.y);
        }
    }

    float d[16][4];
#pragma unroll
    for (int t = 0; t < 16; t++)
#pragma unroll
        for (int j = 0; j < 4; j++) d[t][j] = 0.f;
    float rs0 = 0.f, rs1 = 0.f;

    for (int i = 0; i < NCHUNK; i++) {
        const int buf = i & 1;

        if (i + 1 < NCHUNK) {
            const int nb = 1 - buf;
            const int k0 = (i + 1) * CHK;
#pragma unroll
            for (int p = 0; p < 2; p++) {
                int idx = tid + 256 * p;
                int row = idx >> 4, q = idx & 15;
                cp_async16(sb + (KS_F + nb * CHK * QSTR + row * QSTR + q * 4) * 4,
                           &g_K[(qrow0 + k0 + row) * 64 + q * 4], (k0 + row) < NN);
            }
#pragma unroll
            for (int p = 0; p < 4; p++) {
                int idx = tid + 256 * p;
                int n = idx >> 3, q = idx & 7;
                cp_async16(sb + (VT_F + nb * 128 * VTSTR + n * VTSTR + q * 4) * 4,
                           &g_VT[(size_t)(ns * 128 + n) * 2048 + k0 + q * 4], true);
            }
            cp_commit();
        }

        const float2* KsF2 = (const float2*)(sm + KS_F + buf * CHK * QSTR);
        float s[4][4];
#pragma unroll
        for (int t = 0; t < 4; t++)
#pragma unroll
            for (int j = 0; j < 4; j++) s[t][j] = 0.f;

#pragma unroll
        for (int ks = 0; ks < 8; ks++) {
#pragma unroll
            for (int nt = 0; nt < 4; nt++) {
                float2 kb = KsF2[(8 * nt + g) * (QSTR / 2) + ks * 4 + c];
                mma16n8k8(s[nt], qa[ks][0], qa[ks][1], qa[ks][2], qa[ks][3],
                          __float_as_uint(kb.x), __float_as_uint(kb.y));
            }
        }

        const float2* VtF2 = (const float2*)(sm + VT_F + buf * 128 * VTSTR);
#pragma unroll
        for (int ks = 0; ks < 4; ks++) {
            float p0 = __expf(s[ks][0] * SCALE);
            float p1 = __expf(s[ks][1] * SCALE);
            float p2 = __expf(s[ks][2] * SCALE);
            float p3 = __expf(s[ks][3] * SCALE);
            if (i == NCHUNK - 1) {
                int kc = i * CHK + 8 * ks + 2 * c;
                if (kc     >= NN) { p0 = 0.f; p2 = 0.f; }
                if (kc + 1 >= NN) { p1 = 0.f; p3 = 0.f; }
            }
            rs0 += p0 + p1;
            rs1 += p2 + p3;
            uint32_t a0 = to_tf32(p0), a1 = to_tf32(p2);
            uint32_t a2 = to_tf32(p1), a3 = to_tf32(p3);
#pragma unroll
            for (int nt = 0; nt < 16; nt++) {
                float2 vb = VtF2[(8 * nt + g) * (VTSTR / 2) + ks * 4 + c];
                mma16n8k8(d[nt], a0, a1, a2, a3,
                          __float_as_uint(vb.x), __float_as_uint(vb.y));
            }
        }

        cp_wait0();
        __syncthreads();
    }

    rs0 += __shfl_xor_sync(0xffffffffu, rs0, 1);
    rs0 += __shfl_xor_sync(0xffffffffu, rs0, 2);
    rs1 += __shfl_xor_sync(0xffffffffu, rs1, 1);
    rs1 += __shfl_xor_sync(0xffffffffu, rs1, 2);
    const float inv0 = 1.f / rs0, inv1 = 1.f / rs1;

    const int r0 = n0 + mr + g;
    const int r1 = r0 + 8;
    float* o0 = out + (qrow0 + r0) * 384 + ns * 128 + 2 * c;
    float* o1 = out + (qrow0 + r1) * 384 + ns * 128 + 2 * c;
#pragma unroll
    for (int nt = 0; nt < 16; nt++) {
        if (r0 < NN) *(float2*)(o0 + 8 * nt) = make_float2(d[nt][0] * inv0, d[nt][1] * inv0);
        if (r1 < NN) *(float2*)(o1 + 8 * nt) = make_float2(d[nt][2] * inv1, d[nt][3] * inv1);
    }
}

// ===========================================================================
// Kernel 3: time-attention weight + broadcast add (in place on out).
// ===========================================================================
__global__ __launch_bounds__(256) void k_time(
    const float* __restrict__ x, const float* __restrict__ Win,
    float* __restrict__ out)
{
    const int wid = threadIdx.x >> 5, lane = threadIdx.x & 31;
    const long node = (long)blockIdx.x * 8 + wid;
    __shared__ float qs[8][17];

    const float* xl = x + node * 384 + 368;
    float* dat = out + node * 384;

    if (lane < 16) {
        float q = 0.f;
#pragma unroll
        for (int d = 0; d < 16; d++) q += xl[d] * Win[d * 16 + lane];
        qs[wid][lane] = q;
    }
    __syncwarp();

    float att = -1e30f;
    if (lane < 24) {
        float a = 0.f;
#pragma unroll
        for (int d = 0; d < 16; d++) a += qs[wid][d] * dat[lane * 16 + d];
        att = a;
    }
    float mx = att;
#pragma unroll
    for (int m = 16; m >= 1; m >>= 1)
        mx = fmaxf(mx, __shfl_xor_sync(0xffffffffu, mx, m));
    float e = (lane < 24) ? __expf(att - mx) : 0.f;
    float s = e;
#pragma unroll
    for (int m = 16; m >= 1; m >>= 1)
        s += __shfl_xor_sync(0xffffffffu, s, m);
    float wgt = e / s;

#pragma unroll
    for (int jj = 0; jj < 12; jj++) {
        int i = lane + 32 * jj;
        int t = i >> 4;
        float wt = __shfl_sync(0xffffffffu, wgt, t);
        dat[i] += wt;
    }
}

// ===========================================================================
extern "C" void kernel_launch(void* const* d_in, const int* in_sizes, int n_in,
                              void* d_out, int out_size)
{
    const float* x      = (const float*)d_in[0];
    const float* Wq     = (const float*)d_in[1];
    const float* bq     = (const float*)d_in[2];
    const float* Wk     = (const float*)d_in[3];
    const float* bk     = (const float*)d_in[4];
    const float* g0     = (const float*)d_in[5];
    const float* be0    = (const float*)d_in[6];
    const float* g1     = (const float*)d_in[7];
    const float* be1    = (const float*)d_in[8];
    const float* normal = (const float*)d_in[9];
    const float* Win    = (const float*)d_in[10];
    float* out = (float*)d_out;

    cudaFuncSetAttribute(k_proj_mma, cudaFuncAttributeMaxDynamicSharedMemorySize, KP_SMEM);
    cudaFuncSetAttribute(k_attn_mma, cudaFuncAttributeMaxDynamicSharedMemorySize, SMEM_SZ);

    k_proj_mma<<<(BATCH * NN) / 64, 256, KP_SMEM>>>(x, Wq, bq, Wk, bk, g0, be0, g1, be1);
    k_transpose<<<dim3(64, 12), 256>>>(normal);
    k_attn_mma<<<dim3(16, 3, BATCH), 256, SMEM_SZ>>>(out);
    k_time<<<(BATCH * NN) / 8, 256>>>(x, Win, out);
}

// round 11
// speedup vs baseline: 4.3985x; 1.1166x over previous
#include <cuda_runtime.h>
#include <cstdint>
#include <math.h>

#define BATCH 32
#define NN    2000
#define EMB   64

// scratch
__device__ float g_Q[BATCH * NN * EMB];   // LN q, tf32-rounded, e-cols permuted
__device__ float g_K[BATCH * NN * EMB];   // LN k, tf32-rounded, e-cols permuted
__device__ float g_VT[384 * 2048];        // normal^T, tf32-rounded, keys>=2000 zero

// ===========================================================================
// helpers
// ===========================================================================
__device__ __forceinline__ uint32_t smem_u32(const void* p) {
    uint32_t a;
    asm("{ .reg .u64 t; cvta.to.shared.u64 t, %1; cvt.u32.u64 %0, t; }" : "=r"(a) : "l"(p));
    return a;
}
__device__ __forceinline__ void cp_async16(uint32_t dst, const void* src, bool pred) {
    int sz = pred ? 16 : 0;
    asm volatile("cp.async.cg.shared.global [%0], [%1], 16, %2;\n"
                 :: "r"(dst), "l"(src), "r"(sz));
}
__device__ __forceinline__ void cp_commit() { asm volatile("cp.async.commit_group;"); }
__device__ __forceinline__ void cp_wait0()  { asm volatile("cp.async.wait_group 0;" ::: "memory"); }

__device__ __forceinline__ uint32_t to_tf32(float f) {
    uint32_t r;
    asm("cvt.rna.tf32.f32 %0, %1;" : "=r"(r) : "f"(f));
    return r;
}
__device__ __forceinline__ float to_tf32f(float f) {
    return __uint_as_float(to_tf32(f));
}

// D += A(16x8,row) * B(8x8,col)   tf32
__device__ __forceinline__ void mma16n8k8(float* d,
    uint32_t a0, uint32_t a1, uint32_t a2, uint32_t a3,
    uint32_t b0, uint32_t b1)
{
    asm volatile("mma.sync.aligned.m16n8k8.row.col.f32.tf32.tf32.f32 "
        "{%0,%1,%2,%3}, {%4,%5,%6,%7}, {%8,%9}, {%0,%1,%2,%3};"
        : "+f"(d[0]), "+f"(d[1]), "+f"(d[2]), "+f"(d[3])
        : "r"(a0), "r"(a1), "r"(a2), "r"(a3), "r"(b0), "r"(b1));
}

// column permutation within 8-groups: slot j -> position (j<4 ? 2j : 2j-7)
__device__ __forceinline__ int permcol(int o) {
    int j = o & 7;
    return (o & ~7) | ((j < 4) ? (2 * j) : (2 * j - 7));
}

// ===========================================================================
// Kernel 1: q = LN(xf@Wq+bq), k = LN(xf@Wk+bk) on tensor cores.
// CTA = 64 rows x 128 outs (q|k). K=384 in 8 double-buffered chunks of 48
// (smaller chunks -> 79KB smem -> occupancy 2).
// ===========================================================================
#define KP_XSTR 52
#define KP_WSTR 132
#define KP_XBUF (64 * KP_XSTR)             // 3328
#define KP_WBUF (48 * KP_WSTR)             // 6336
#define KP_XS   0                          // 2 * 3328 = 6656
#define KP_WS   6656                       // 2 * 6336 = 12672
#define KP_PB   19328
#define KP_PG   19456
#define KP_PBE  19584
#define KP_SMF  19712
#define KP_SMEM (KP_SMF * 4)               // 78848 bytes

__global__ __launch_bounds__(256, 2) void k_proj_mma(
    const float* __restrict__ x,
    const float* __restrict__ Wq, const float* __restrict__ bq,
    const float* __restrict__ Wk, const float* __restrict__ bk,
    const float* __restrict__ g0, const float* __restrict__ be0,
    const float* __restrict__ g1, const float* __restrict__ be1)
{
    extern __shared__ float sp[];
    const uint32_t sb = smem_u32(sp);
    const int tid  = threadIdx.x;
    const int w    = tid >> 5;
    const int lane = tid & 31;
    const int g    = lane >> 2;
    const int c    = lane & 3;
    const int rw   = w & 3,  ow = w >> 2;
    const int rbase = rw * 16;
    const int n0    = ow * 64;
    const long R0 = (long)blockIdx.x * 64;

    // stage LN params
    if (tid < 128) {
        int o = tid;
        sp[KP_PB  + o] = (o < 64) ? bq[o]  : bk[o - 64];
        sp[KP_PG  + o] = (o < 64) ? g0[o]  : g1[o - 64];
        sp[KP_PBE + o] = (o < 64) ? be0[o] : be1[o - 64];
    }

    // preload chunk 0
#pragma unroll
    for (int p = 0; p < 3; p++) {              // x: 64 rows x 12 quads
        int idx = tid + 256 * p;
        int row = idx / 12, qd = idx % 12;
        cp_async16(sb + (KP_XS + row * KP_XSTR + qd * 4) * 4,
                   &x[(R0 + row) * 384 + qd * 4], true);
    }
#pragma unroll
    for (int p = 0; p < 6; p++) {              // W: 48 k-rows x 32 quads
        int idx = tid + 256 * p;
        int k = idx >> 5, qd = idx & 31;
        const float* src = (qd < 16) ? &Wq[(size_t)k * 64 + qd * 4]
                                     : &Wk[(size_t)k * 64 + (qd - 16) * 4];
        cp_async16(sb + (KP_WS + k * KP_WSTR + qd * 4) * 4, src, true);
    }
    cp_commit();

    float d[8][4];
#pragma unroll
    for (int t = 0; t < 8; t++)
#pragma unroll
        for (int j = 0; j < 4; j++) d[t][j] = 0.f;

    for (int ch = 0; ch < 8; ch++) {
        cp_wait0();
        __syncthreads();

        if (ch < 7) {
            const int nb = (ch + 1) & 1;
            const int kc = (ch + 1) * 48;
#pragma unroll
            for (int p = 0; p < 3; p++) {
                int idx = tid + 256 * p;
                int row = idx / 12, qd = idx % 12;
                cp_async16(sb + (KP_XS + nb * KP_XBUF + row * KP_XSTR + qd * 4) * 4,
                           &x[(R0 + row) * 384 + kc + qd * 4], true);
            }
#pragma unroll
            for (int p = 0; p < 6; p++) {
                int idx = tid + 256 * p;
                int k = idx >> 5, qd = idx & 31;
                const float* src = (qd < 16) ? &Wq[(size_t)(kc + k) * 64 + qd * 4]
                                             : &Wk[(size_t)(kc + k) * 64 + (qd - 16) * 4];
                cp_async16(sb + (KP_WS + nb * KP_WBUF + k * KP_WSTR + qd * 4) * 4, src, true);
            }
            cp_commit();
        }

        const float* xs = sp + KP_XS + (ch & 1) * KP_XBUF;
        const float* ws = sp + KP_WS + (ch & 1) * KP_WBUF;

#pragma unroll
        for (int ks = 0; ks < 6; ks++) {
            const int kk = ks * 8;
            uint32_t a0 = to_tf32(xs[(rbase + g)     * KP_XSTR + kk + c]);
            uint32_t a1 = to_tf32(xs[(rbase + g + 8) * KP_XSTR + kk + c]);
            uint32_t a2 = to_tf32(xs[(rbase + g)     * KP_XSTR + kk + c + 4]);
            uint32_t a3 = to_tf32(xs[(rbase + g + 8) * KP_XSTR + kk + c + 4]);
#pragma unroll
            for (int nt = 0; nt < 8; nt++) {
                uint32_t b0 = to_tf32(ws[(kk + c)     * KP_WSTR + n0 + nt * 8 + g]);
                uint32_t b1 = to_tf32(ws[(kk + c + 4) * KP_WSTR + n0 + nt * 8 + g]);
                mma16n8k8(d[nt], a0, a1, a2, a3, b0, b1);
            }
        }
    }

    // ---- epilogue: bias + LN (quad-reduced) + permuted tf32 store ----
    float v[8][4];
    float s0 = 0.f, q0 = 0.f, s1 = 0.f, q1 = 0.f;
#pragma unroll
    for (int nt = 0; nt < 8; nt++)
#pragma unroll
        for (int j = 0; j < 4; j++) {
            int col = n0 + nt * 8 + 2 * c + (j & 1);
            float t = d[nt][j] + sp[KP_PB + col];
            v[nt][j] = t;
            if (j < 2) { s0 += t; q0 += t * t; }
            else       { s1 += t; q1 += t * t; }
        }
#pragma unroll
    for (int m = 1; m <= 2; m <<= 1) {
        s0 += __shfl_xor_sync(0xffffffffu, s0, m);
        q0 += __shfl_xor_sync(0xffffffffu, q0, m);
        s1 += __shfl_xor_sync(0xffffffffu, s1, m);
        q1 += __shfl_xor_sync(0xffffffffu, q1, m);
    }
    const float mu0 = s0 * (1.f / 64.f);
    const float r0v = rsqrtf(q0 * (1.f / 64.f) - mu0 * mu0 + 1e-5f);
    const float mu1 = s1 * (1.f / 64.f);
    const float r1v = rsqrtf(q1 * (1.f / 64.f) - mu1 * mu1 + 1e-5f);

    float* dst = ow ? g_K : g_Q;
    const long base0 = (R0 + rbase + g) * 64;
    const long base1 = base0 + 8 * 64;
#pragma unroll
    for (int nt = 0; nt < 8; nt++)
#pragma unroll
        for (int par = 0; par < 2; par++) {
            int o   = nt * 8 + 2 * c + par;
            int col = n0 + o;
            int pos = permcol(o);
            float gv = sp[KP_PG + col], bev = sp[KP_PBE + col];
            dst[base0 + pos] = to_tf32f((v[nt][par]     - mu0) * r0v * gv + bev);
            dst[base1 + pos] = to_tf32f((v[nt][2 + par] - mu1) * r1v * gv + bev);
        }
}

// ===========================================================================
// Kernel 1b: transpose normal (2000x384) -> g_VT (384x2048), tf32, zero pad
// ===========================================================================
__global__ __launch_bounds__(256) void k_transpose(const float* __restrict__ normal)
{
    __shared__ float t[32][33];
    const int m0 = blockIdx.x * 32;
    const int c0 = blockIdx.y * 32;
    const int tx = threadIdx.x & 31, ty = threadIdx.x >> 5;
#pragma unroll
    for (int p = 0; p < 4; p++) {
        int m = m0 + ty + 8 * p;
        t[ty + 8 * p][tx] = (m < NN) ? to_tf32f(normal[(long)m * 384 + c0 + tx]) : 0.f;
    }
    __syncthreads();
#pragma unroll
    for (int p = 0; p < 4; p++) {
        int c = c0 + ty + 8 * p;
        g_VT[(long)c * 2048 + m0 + tx] = t[tx][ty + 8 * p];
    }
}

// ===========================================================================
// Kernel 2: flash node-attention, mma.sync tf32.
// NOW 2 col-slices of 192 (was 3x128): grid 16 x 2 x 32 = 1024 CTAs -> 6.92
// waves at occ 1 (quantization 99%), and QK+exp duplication drops 3x -> 2x.
// d[24][4] accumulator (~96 regs) + qa (~32) => occ 1.
// ===========================================================================
#define CHK    32
#define NCHUNK 63
#define QSTR   72
#define VTSTR  40
#define NSLC   192           // cols per slice

#define QS_F  0
#define KS_F  (128 * QSTR)                 // 9216
#define VT_F  (KS_F + 2 * CHK * QSTR)      // 13824
#define SMF   (VT_F + 2 * NSLC * VTSTR)    // 29184 floats
#define SMEM_SZ (SMF * 4)                  // 116736 bytes

__global__ __launch_bounds__(256, 1) void k_attn_mma(float* __restrict__ out)
{
    extern __shared__ float sm[];
    const uint32_t sb = smem_u32(sm);
    const int tid  = threadIdx.x;
    const int w    = tid >> 5;
    const int lane = tid & 31;
    const int g    = lane >> 2;
    const int c    = lane & 3;
    const int mt = blockIdx.x, ns = blockIdx.y, b = blockIdx.z;
    const int n0 = mt * 128;
    const int mr = w * 16;
    const float SCALE = 0.02236067977f;
    const long qrow0 = (long)b * NN;

#pragma unroll
    for (int p = 0; p < 8; p++) {                  // Q: 2048 quads
        int idx = tid + 256 * p;
        int row = idx >> 4, q = idx & 15;
        cp_async16(sb + (QS_F + row * QSTR + q * 4) * 4,
                   &g_Q[(qrow0 + n0 + row) * 64 + q * 4], (n0 + row) < NN);
    }
#pragma unroll
    for (int p = 0; p < 2; p++) {                  // K chunk0: 512 quads
        int idx = tid + 256 * p;
        int row = idx >> 4, q = idx & 15;
        cp_async16(sb + (KS_F + row * QSTR + q * 4) * 4,
                   &g_K[(qrow0 + row) * 64 + q * 4], row < NN);
    }
#pragma unroll
    for (int p = 0; p < 6; p++) {                  // Vt chunk0: 1536 quads
        int idx = tid + 256 * p;
        int n = idx >> 3, q = idx & 7;
        cp_async16(sb + (VT_F + n * VTSTR + q * 4) * 4,
                   &g_VT[(size_t)(ns * NSLC + n) * 2048 + q * 4], true);
    }
    cp_commit();
    cp_wait0();
    __syncthreads();

    // Q fragments -> registers (loop invariant)
    uint32_t qa[8][4];
    {
        const float2* q0 = (const float2*)(sm + QS_F + (mr + g) * QSTR);
        const float2* q1 = (const float2*)(sm + QS_F + (mr + g + 8) * QSTR);
#pragma unroll
        for (int ks = 0; ks < 8; ks++) {
            float2 x0 = q0[ks * 4 + c];
            float2 x1 = q1[ks * 4 + c];
            qa[ks][0] = __float_as_uint(x0.x);
            qa[ks][1] = __float_as_uint(x1.x);
            qa[ks][2] = __float_as_uint(x0.y);
            qa[ks][3] = __float_as_uint(x1.y);
        }
    }

    float d[24][4];
#pragma unroll
    for (int t = 0; t < 24; t++)
#pragma unroll
        for (int j = 0; j < 4; j++) d[t][j] = 0.f;
    float rs0 = 0.f, rs1 = 0.f;

    for (int i = 0; i < NCHUNK; i++) {
        const int buf = i & 1;

        if (i + 1 < NCHUNK) {
            const int nb = 1 - buf;
            const int k0 = (i + 1) * CHK;
#pragma unroll
            for (int p = 0; p < 2; p++) {
                int idx = tid + 256 * p;
                int row = idx >> 4, q = idx & 15;
                cp_async16(sb + (KS_F + nb * CHK * QSTR + row * QSTR + q * 4) * 4,
                           &g_K[(qrow0 + k0 + row) * 64 + q * 4], (k0 + row) < NN);
            }
#pragma unroll
            for (int p = 0; p < 6; p++) {
                int idx = tid + 256 * p;
                int n = idx >> 3, q = idx & 7;
                cp_async16(sb + (VT_F + nb * NSLC * VTSTR + n * VTSTR + q * 4) * 4,
                           &g_VT[(size_t)(ns * NSLC + n) * 2048 + k0 + q * 4], true);
            }
            cp_commit();
        }

        // mma1: S = Q K^T
        const float2* KsF2 = (const float2*)(sm + KS_F + buf * CHK * QSTR);
        float s[4][4];
#pragma unroll
        for (int t = 0; t < 4; t++)
#pragma unroll
            for (int j = 0; j < 4; j++) s[t][j] = 0.f;

#pragma unroll
        for (int ks = 0; ks < 8; ks++) {
#pragma unroll
            for (int nt = 0; nt < 4; nt++) {
                float2 kb = KsF2[(8 * nt + g) * (QSTR / 2) + ks * 4 + c];
                mma16n8k8(s[nt], qa[ks][0], qa[ks][1], qa[ks][2], qa[ks][3],
                          __float_as_uint(kb.x), __float_as_uint(kb.y));
            }
        }

        // fused exp + rowsum + mma2 (P in registers, slot-permuted)
        const float2* VtF2 = (const float2*)(sm + VT_F + buf * NSLC * VTSTR);
#pragma unroll
        for (int ks = 0; ks < 4; ks++) {
            float p0 = __expf(s[ks][0] * SCALE);
            float p1 = __expf(s[ks][1] * SCALE);
            float p2 = __expf(s[ks][2] * SCALE);
            float p3 = __expf(s[ks][3] * SCALE);
            if (i == NCHUNK - 1) {
                int kc = i * CHK + 8 * ks + 2 * c;
                if (kc     >= NN) { p0 = 0.f; p2 = 0.f; }
                if (kc + 1 >= NN) { p1 = 0.f; p3 = 0.f; }
            }
            rs0 += p0 + p1;
            rs1 += p2 + p3;
            uint32_t a0 = to_tf32(p0), a1 = to_tf32(p2);
            uint32_t a2 = to_tf32(p1), a3 = to_tf32(p3);
#pragma unroll
            for (int nt = 0; nt < 24; nt++) {
                float2 vb = VtF2[(8 * nt + g) * (VTSTR / 2) + ks * 4 + c];
                mma16n8k8(d[nt], a0, a1, a2, a3,
                          __float_as_uint(vb.x), __float_as_uint(vb.y));
            }
        }

        cp_wait0();
        __syncthreads();
    }

    // epilogue
    rs0 += __shfl_xor_sync(0xffffffffu, rs0, 1);
    rs0 += __shfl_xor_sync(0xffffffffu, rs0, 2);
    rs1 += __shfl_xor_sync(0xffffffffu, rs1, 1);
    rs1 += __shfl_xor_sync(0xffffffffu, rs1, 2);
    const float inv0 = 1.f / rs0, inv1 = 1.f / rs1;

    const int r0 = n0 + mr + g;
    const int r1 = r0 + 8;
    float* o0 = out + (qrow0 + r0) * 384 + ns * NSLC + 2 * c;
    float* o1 = out + (qrow0 + r1) * 384 + ns * NSLC + 2 * c;
#pragma unroll
    for (int nt = 0; nt < 24; nt++) {
        if (r0 < NN) *(float2*)(o0 + 8 * nt) = make_float2(d[nt][0] * inv0, d[nt][1] * inv0);
        if (r1 < NN) *(float2*)(o1 + 8 * nt) = make_float2(d[nt][2] * inv1, d[nt][3] * inv1);
    }
}

// ===========================================================================
// Kernel 3: time-attention weight + broadcast add (in place on out).
// ===========================================================================
__global__ __launch_bounds__(256) void k_time(
    const float* __restrict__ x, const float* __restrict__ Win,
    float* __restrict__ out)
{
    const int wid = threadIdx.x >> 5, lane = threadIdx.x & 31;
    const long node = (long)blockIdx.x * 8 + wid;
    __shared__ float qs[8][17];

    const float* xl = x + node * 384 + 368;
    float* dat = out + node * 384;

    if (lane < 16) {
        float q = 0.f;
#pragma unroll
        for (int d = 0; d < 16; d++) q += xl[d] * Win[d * 16 + lane];
        qs[wid][lane] = q;
    }
    __syncwarp();

    float att = -1e30f;
    if (lane < 24) {
        float a = 0.f;
#pragma unroll
        for (int d = 0; d < 16; d++) a += qs[wid][d] * dat[lane * 16 + d];
        att = a;
    }
    float mx = att;
#pragma unroll
    for (int m = 16; m >= 1; m >>= 1)
        mx = fmaxf(mx, __shfl_xor_sync(0xffffffffu, mx, m));
    float e = (lane < 24) ? __expf(att - mx) : 0.f;
    float s = e;
#pragma unroll
    for (int m = 16; m >= 1; m >>= 1)
        s += __shfl_xor_sync(0xffffffffu, s, m);
    float wgt = e / s;

#pragma unroll
    for (int jj = 0; jj < 12; jj++) {
        int i = lane + 32 * jj;
        int t = i >> 4;
        float wt = __shfl_sync(0xffffffffu, wgt, t);
        dat[i] += wt;
    }
}

// ===========================================================================
extern "C" void kernel_launch(void* const* d_in, const int* in_sizes, int n_in,
                              void* d_out, int out_size)
{
    const float* x      = (const float*)d_in[0];
    const float* Wq     = (const float*)d_in[1];
    const float* bq     = (const float*)d_in[2];
    const float* Wk     = (const float*)d_in[3];
    const float* bk     = (const float*)d_in[4];
    const float* g0     = (const float*)d_in[5];
    const float* be0    = (const float*)d_in[6];
    const float* g1     = (const float*)d_in[7];
    const float* be1    = (const float*)d_in[8];
    const float* normal = (const float*)d_in[9];
    const float* Win    = (const float*)d_in[10];
    float* out = (float*)d_out;

    cudaFuncSetAttribute(k_proj_mma, cudaFuncAttributeMaxDynamicSharedMemorySize, KP_SMEM);
    cudaFuncSetAttribute(k_attn_mma, cudaFuncAttributeMaxDynamicSharedMemorySize, SMEM_SZ);

    k_proj_mma<<<(BATCH * NN) / 64, 256, KP_SMEM>>>(x, Wq, bq, Wk, bk, g0, be0, g1, be1);
    k_transpose<<<dim3(64, 12), 256>>>(normal);
    k_attn_mma<<<dim3(16, 2, BATCH), 256, SMEM_SZ>>>(out);
    k_time<<<(BATCH * NN) / 8, 256>>>(x, Win, out);
}

// round 13
// speedup vs baseline: 5.1099x; 1.1617x over previous
#include <cuda_runtime.h>
#include <cuda_fp16.h>
#include <cstdint>
#include <math.h>

#define BATCH 32
#define NN    2000
#define EMB   64

// scratch
__device__ __half g_Qh[BATCH * NN * EMB];  // LN q, fp16, cols interleave-permuted
__device__ __half g_Kh[BATCH * NN * EMB];  // LN k, fp16, cols interleave-permuted
__device__ __half g_VTh[384 * 2048];       // normal^T fp16, keys perm, >=2000 zero

// ===========================================================================
// helpers
// ===========================================================================
__device__ __forceinline__ uint32_t smem_u32(const void* p) {
    uint32_t a;
    asm("{ .reg .u64 t; cvta.to.shared.u64 t, %1; cvt.u32.u64 %0, t; }" : "=r"(a) : "l"(p));
    return a;
}
__device__ __forceinline__ void cp_async16(uint32_t dst, const void* src, bool pred) {
    int sz = pred ? 16 : 0;
    asm volatile("cp.async.cg.shared.global [%0], [%1], 16, %2;\n"
                 :: "r"(dst), "l"(src), "r"(sz));
}
__device__ __forceinline__ void cp_commit() { asm volatile("cp.async.commit_group;"); }
__device__ __forceinline__ void cp_wait0()  { asm volatile("cp.async.wait_group 0;" ::: "memory"); }

__device__ __forceinline__ uint32_t to_tf32(float f) {
    uint32_t r;
    asm("cvt.rna.tf32.f32 %0, %1;" : "=r"(r) : "f"(f));
    return r;
}
// pack two f32 -> f16x2 (lo = first arg)
__device__ __forceinline__ uint32_t pack_f16(float lo, float hi) {
    uint32_t r;
    asm("cvt.rn.f16x2.f32 %0, %1, %2;" : "=r"(r) : "f"(hi), "f"(lo));
    return r;
}

// tf32: D += A(16x8) B(8x8)
__device__ __forceinline__ void mma16n8k8(float* d,
    uint32_t a0, uint32_t a1, uint32_t a2, uint32_t a3,
    uint32_t b0, uint32_t b1)
{
    asm volatile("mma.sync.aligned.m16n8k8.row.col.f32.tf32.tf32.f32 "
        "{%0,%1,%2,%3}, {%4,%5,%6,%7}, {%8,%9}, {%0,%1,%2,%3};"
        : "+f"(d[0]), "+f"(d[1]), "+f"(d[2]), "+f"(d[3])
        : "r"(a0), "r"(a1), "r"(a2), "r"(a3), "r"(b0), "r"(b1));
}
// fp16: D(f32) += A(16x16 f16) B(16x8 f16)
__device__ __forceinline__ void mma16n8k16h(float* d,
    uint32_t a0, uint32_t a1, uint32_t a2, uint32_t a3,
    uint32_t b0, uint32_t b1)
{
    asm volatile("mma.sync.aligned.m16n8k16.row.col.f32.f16.f16.f32 "
        "{%0,%1,%2,%3}, {%4,%5,%6,%7}, {%8,%9}, {%0,%1,%2,%3};"
        : "+f"(d[0]), "+f"(d[1]), "+f"(d[2]), "+f"(d[3])
        : "r"(a0), "r"(a1), "r"(a2), "r"(a3), "r"(b0), "r"(b1));
}

// interleave permutation within 16-groups: [0,1,8,9,2,3,10,11,4,5,12,13,6,7,14,15]
// position of logical index o: quad c=(o&7)>>1 holds {2c,2c+1,2c+8,2c+9} at 4c..4c+3
__device__ __forceinline__ int perm16(int o) {
    return (o & ~15) | ((((o & 7) >> 1) << 2) | (((o >> 3) & 1) << 1) | (o & 1));
}

// ===========================================================================
// Kernel 1: q = LN(xf@Wq+bq), k = LN(xf@Wk+bk) on tensor cores (tf32 inside,
// fp16 permuted outputs). CTA = 64 rows x 128 outs, 8 chunks of 48, occ 2.
// ===========================================================================
#define KP_XSTR 52
#define KP_WSTR 132
#define KP_XBUF (64 * KP_XSTR)
#define KP_WBUF (48 * KP_WSTR)
#define KP_XS   0
#define KP_WS   6656
#define KP_PB   19328
#define KP_PG   19456
#define KP_PBE  19584
#define KP_SMF  19712
#define KP_SMEM (KP_SMF * 4)

__global__ __launch_bounds__(256, 2) void k_proj_mma(
    const float* __restrict__ x,
    const float* __restrict__ Wq, const float* __restrict__ bq,
    const float* __restrict__ Wk, const float* __restrict__ bk,
    const float* __restrict__ g0, const float* __restrict__ be0,
    const float* __restrict__ g1, const float* __restrict__ be1)
{
    extern __shared__ float sp[];
    const uint32_t sb = smem_u32(sp);
    const int tid  = threadIdx.x;
    const int w    = tid >> 5;
    const int lane = tid & 31;
    const int g    = lane >> 2;
    const int c    = lane & 3;
    const int rw   = w & 3,  ow = w >> 2;
    const int rbase = rw * 16;
    const int n0    = ow * 64;
    const long R0 = (long)blockIdx.x * 64;

    if (tid < 128) {
        int o = tid;
        sp[KP_PB  + o] = (o < 64) ? bq[o]  : bk[o - 64];
        sp[KP_PG  + o] = (o < 64) ? g0[o]  : g1[o - 64];
        sp[KP_PBE + o] = (o < 64) ? be0[o] : be1[o - 64];
    }

#pragma unroll
    for (int p = 0; p < 3; p++) {
        int idx = tid + 256 * p;
        int row = idx / 12, qd = idx % 12;
        cp_async16(sb + (KP_XS + row * KP_XSTR + qd * 4) * 4,
                   &x[(R0 + row) * 384 + qd * 4], true);
    }
#pragma unroll
    for (int p = 0; p < 6; p++) {
        int idx = tid + 256 * p;
        int k = idx >> 5, qd = idx & 31;
        const float* src = (qd < 16) ? &Wq[(size_t)k * 64 + qd * 4]
                                     : &Wk[(size_t)k * 64 + (qd - 16) * 4];
        cp_async16(sb + (KP_WS + k * KP_WSTR + qd * 4) * 4, src, true);
    }
    cp_commit();

    float d[8][4];
#pragma unroll
    for (int t = 0; t < 8; t++)
#pragma unroll
        for (int j = 0; j < 4; j++) d[t][j] = 0.f;

    for (int ch = 0; ch < 8; ch++) {
        cp_wait0();
        __syncthreads();

        if (ch < 7) {
            const int nb = (ch + 1) & 1;
            const int kc = (ch + 1) * 48;
#pragma unroll
            for (int p = 0; p < 3; p++) {
                int idx = tid + 256 * p;
                int row = idx / 12, qd = idx % 12;
                cp_async16(sb + (KP_XS + nb * KP_XBUF + row * KP_XSTR + qd * 4) * 4,
                           &x[(R0 + row) * 384 + kc + qd * 4], true);
            }
#pragma unroll
            for (int p = 0; p < 6; p++) {
                int idx = tid + 256 * p;
                int k = idx >> 5, qd = idx & 31;
                const float* src = (qd < 16) ? &Wq[(size_t)(kc + k) * 64 + qd * 4]
                                             : &Wk[(size_t)(kc + k) * 64 + (qd - 16) * 4];
                cp_async16(sb + (KP_WS + nb * KP_WBUF + k * KP_WSTR + qd * 4) * 4, src, true);
            }
            cp_commit();
        }

        const float* xs = sp + KP_XS + (ch & 1) * KP_XBUF;
        const float* ws = sp + KP_WS + (ch & 1) * KP_WBUF;

#pragma unroll
        for (int ks = 0; ks < 6; ks++) {
            const int kk = ks * 8;
            uint32_t a0 = to_tf32(xs[(rbase + g)     * KP_XSTR + kk + c]);
            uint32_t a1 = to_tf32(xs[(rbase + g + 8) * KP_XSTR + kk + c]);
            uint32_t a2 = to_tf32(xs[(rbase + g)     * KP_XSTR + kk + c + 4]);
            uint32_t a3 = to_tf32(xs[(rbase + g + 8) * KP_XSTR + kk + c + 4]);
#pragma unroll
            for (int nt = 0; nt < 8; nt++) {
                uint32_t b0 = to_tf32(ws[(kk + c)     * KP_WSTR + n0 + nt * 8 + g]);
                uint32_t b1 = to_tf32(ws[(kk + c + 4) * KP_WSTR + n0 + nt * 8 + g]);
                mma16n8k8(d[nt], a0, a1, a2, a3, b0, b1);
            }
        }
    }

    // epilogue: bias + LN + fp16 permuted store
    float v[8][4];
    float s0 = 0.f, q0 = 0.f, s1 = 0.f, q1 = 0.f;
#pragma unroll
    for (int nt = 0; nt < 8; nt++)
#pragma unroll
        for (int j = 0; j < 4; j++) {
            int col = n0 + nt * 8 + 2 * c + (j & 1);
            float t = d[nt][j] + sp[KP_PB + col];
            v[nt][j] = t;
            if (j < 2) { s0 += t; q0 += t * t; }
            else       { s1 += t; q1 += t * t; }
        }
#pragma unroll
    for (int m = 1; m <= 2; m <<= 1) {
        s0 += __shfl_xor_sync(0xffffffffu, s0, m);
        q0 += __shfl_xor_sync(0xffffffffu, q0, m);
        s1 += __shfl_xor_sync(0xffffffffu, s1, m);
        q1 += __shfl_xor_sync(0xffffffffu, q1, m);
    }
    const float mu0 = s0 * (1.f / 64.f);
    const float r0v = rsqrtf(q0 * (1.f / 64.f) - mu0 * mu0 + 1e-5f);
    const float mu1 = s1 * (1.f / 64.f);
    const float r1v = rsqrtf(q1 * (1.f / 64.f) - mu1 * mu1 + 1e-5f);

    __half* dst = ow ? g_Kh : g_Qh;
    const long base0 = (R0 + rbase + g) * 64;
    const long base1 = base0 + 8 * 64;
#pragma unroll
    for (int nt = 0; nt < 8; nt++)
#pragma unroll
        for (int par = 0; par < 2; par++) {
            int o   = nt * 8 + 2 * c + par;
            int col = n0 + o;
            int pos = perm16(o);
            float gv = sp[KP_PG + col], bev = sp[KP_PBE + col];
            dst[base0 + pos] = __float2half((v[nt][par]     - mu0) * r0v * gv + bev);
            dst[base1 + pos] = __float2half((v[nt][2 + par] - mu1) * r1v * gv + bev);
        }
}

// ===========================================================================
// Kernel 1b: transpose normal -> g_VTh (384 x 2048 fp16), key-permuted, pad 0
// ===========================================================================
__global__ __launch_bounds__(256) void k_transpose(const float* __restrict__ normal)
{
    __shared__ float t[32][33];
    const int m0 = blockIdx.x * 32;
    const int c0 = blockIdx.y * 32;
    const int tx = threadIdx.x & 31, ty = threadIdx.x >> 5;
#pragma unroll
    for (int p = 0; p < 4; p++) {
        int m = m0 + ty + 8 * p;
        t[ty + 8 * p][tx] = (m < NN) ? normal[(long)m * 384 + c0 + tx] : 0.f;
    }
    __syncthreads();
    const int pm = perm16(tx);
#pragma unroll
    for (int p = 0; p < 4; p++) {
        int c = c0 + ty + 8 * p;
        g_VTh[(long)c * 2048 + m0 + pm] = __float2half(t[tx][ty + 8 * p]);
    }
}

// ===========================================================================
// Kernel 2: flash node-attention, fp16 mma.sync m16n8k16.
// grid (16 x 2 x 32), 256 threads. P maps C-frag -> A-frag directly.
// ===========================================================================
#define CHK    32
#define NCHUNK 63
#define QSTR_H 72            // halves (64 data + 8 pad)
#define VSTR_H 40            // halves (32 keys + 8 pad)
#define NSLC   192

#define QS_H  0                            // 128*72 = 9216 h
#define KS_H  (128 * QSTR_H)               // 2*32*72 = 4608 h
#define VT_H  (KS_H + 2 * CHK * QSTR_H)    // 2*192*40 = 15360 h
#define SMH   (VT_H + 2 * NSLC * VSTR_H)   // 29184 halves
#define SMEM_SZ (SMH * 2)                  // 58368 bytes

__global__ __launch_bounds__(256, 1) void k_attn_mma(float* __restrict__ out)
{
    extern __shared__ __half smh[];
    const uint32_t sb = smem_u32(smh);
    const int tid  = threadIdx.x;
    const int w    = tid >> 5;
    const int lane = tid & 31;
    const int g    = lane >> 2;
    const int c    = lane & 3;
    const int mt = blockIdx.x, ns = blockIdx.y, b = blockIdx.z;
    const int n0 = mt * 128;
    const int mr = w * 16;
    const float SCALE = 0.02236067977f;
    const long qrow0 = (long)b * NN;

    // ---- initial loads: Q tile + chunk 0 K/V (fp16: 16B = 8 halves) ----
#pragma unroll
    for (int p = 0; p < 4; p++) {                  // Q: 128 rows x 8 quads
        int idx = tid + 256 * p;
        int row = idx >> 3, q = idx & 7;
        cp_async16(sb + (row * QSTR_H + q * 8) * 2,
                   &g_Qh[(qrow0 + n0 + row) * 64 + q * 8], (n0 + row) < NN);
    }
    {                                              // K chunk0: 32 rows x 8 quads
        int row = tid >> 3, q = tid & 7;
        cp_async16(sb + (KS_H + row * QSTR_H + q * 8) * 2,
                   &g_Kh[(qrow0 + row) * 64 + q * 8], row < NN);
    }
#pragma unroll
    for (int p = 0; p < 3; p++) {                  // Vt chunk0: 192 rows x 4 quads
        int idx = tid + 256 * p;
        int n = idx >> 2, q = idx & 3;
        cp_async16(sb + (VT_H + n * VSTR_H + q * 8) * 2,
                   &g_VTh[(size_t)(ns * NSLC + n) * 2048 + q * 8], true);
    }
    cp_commit();
    cp_wait0();
    __syncthreads();

    // ---- Q fragments -> registers (4 k-groups of 16) ----
    uint32_t qa[4][4];
    {
        const uint2* q0 = (const uint2*)(smh + (mr + g) * QSTR_H);
        const uint2* q1 = (const uint2*)(smh + (mr + g + 8) * QSTR_H);
#pragma unroll
        for (int ks = 0; ks < 4; ks++) {
            uint2 x0 = q0[ks * 4 + c];
            uint2 x1 = q1[ks * 4 + c];
            qa[ks][0] = x0.x;   // row g,   k 2c,2c+1
            qa[ks][1] = x1.x;   // row g+8, k 2c,2c+1
            qa[ks][2] = x0.y;   // row g,   k 2c+8,2c+9
            qa[ks][3] = x1.y;   // row g+8, k 2c+8,2c+9
        }
    }

    float d[24][4];
#pragma unroll
    for (int t = 0; t < 24; t++)
#pragma unroll
        for (int j = 0; j < 4; j++) d[t][j] = 0.f;
    float rs0 = 0.f, rs1 = 0.f;

    for (int i = 0; i < NCHUNK; i++) {
        const int buf = i & 1;

        if (i + 1 < NCHUNK) {
            const int nb = 1 - buf;
            const int k0 = (i + 1) * CHK;
            {
                int row = tid >> 3, q = tid & 7;
                cp_async16(sb + (KS_H + nb * CHK * QSTR_H + row * QSTR_H + q * 8) * 2,
                           &g_Kh[(qrow0 + k0 + row) * 64 + q * 8], (k0 + row) < NN);
            }
#pragma unroll
            for (int p = 0; p < 3; p++) {
                int idx = tid + 256 * p;
                int n = idx >> 2, q = idx & 3;
                cp_async16(sb + (VT_H + nb * NSLC * VSTR_H + n * VSTR_H + q * 8) * 2,
                           &g_VTh[(size_t)(ns * NSLC + n) * 2048 + k0 + q * 8], true);
            }
            cp_commit();
        }

        // ---- mma1: S = Q K^T  (4 k-groups x 4 n-tiles) ----
        const uint2* Kp = (const uint2*)(smh + KS_H + buf * CHK * QSTR_H);
        float s[4][4];
#pragma unroll
        for (int t = 0; t < 4; t++)
#pragma unroll
            for (int j = 0; j < 4; j++) s[t][j] = 0.f;

#pragma unroll
        for (int ks = 0; ks < 4; ks++) {
#pragma unroll
            for (int nt = 0; nt < 4; nt++) {
                uint2 kb = Kp[(8 * nt + g) * (QSTR_H / 4) + ks * 4 + c];
                mma16n8k16h(s[nt], qa[ks][0], qa[ks][1], qa[ks][2], qa[ks][3],
                            kb.x, kb.y);
            }
        }

        // ---- fused exp + rowsum + mma2 (P: C-frag -> A-frag, in regs) ----
        const uint2* Vp = (const uint2*)(smh + VT_H + buf * NSLC * VSTR_H);
#pragma unroll
        for (int ks2 = 0; ks2 < 2; ks2++) {
            const int t0 = 2 * ks2, t1 = t0 + 1;
            float p00 = __expf(s[t0][0] * SCALE);   // row g,   key 8t0+2c
            float p01 = __expf(s[t0][1] * SCALE);   // row g,   key 8t0+2c+1
            float p02 = __expf(s[t0][2] * SCALE);   // row g+8, key 8t0+2c
            float p03 = __expf(s[t0][3] * SCALE);
            float p10 = __expf(s[t1][0] * SCALE);   // row g,   key 8t1+2c
            float p11 = __expf(s[t1][1] * SCALE);
            float p12 = __expf(s[t1][2] * SCALE);
            float p13 = __expf(s[t1][3] * SCALE);
            if (i == NCHUNK - 1) {
                int kc0 = i * CHK + 8 * t0 + 2 * c;
                int kc1 = i * CHK + 8 * t1 + 2 * c;
                if (kc0     >= NN) { p00 = 0.f; p02 = 0.f; }
                if (kc0 + 1 >= NN) { p01 = 0.f; p03 = 0.f; }
                if (kc1     >= NN) { p10 = 0.f; p12 = 0.f; }
                if (kc1 + 1 >= NN) { p11 = 0.f; p13 = 0.f; }
            }
            rs0 += p00 + p01 + p10 + p11;
            rs1 += p02 + p03 + p12 + p13;
            // A-fragment: a0 row g keys {2c,2c+1}; a2 keys {2c+8,2c+9} (=tile t1)
            uint32_t a0 = pack_f16(p00, p01);
            uint32_t a1 = pack_f16(p02, p03);
            uint32_t a2 = pack_f16(p10, p11);
            uint32_t a3 = pack_f16(p12, p13);
#pragma unroll
            for (int nt = 0; nt < 24; nt++) {
                uint2 vb = Vp[(8 * nt + g) * (VSTR_H / 4) + ks2 * 4 + c];
                mma16n8k16h(d[nt], a0, a1, a2, a3, vb.x, vb.y);
            }
        }

        cp_wait0();
        __syncthreads();
    }

    // ---- epilogue ----
    rs0 += __shfl_xor_sync(0xffffffffu, rs0, 1);
    rs0 += __shfl_xor_sync(0xffffffffu, rs0, 2);
    rs1 += __shfl_xor_sync(0xffffffffu, rs1, 1);
    rs1 += __shfl_xor_sync(0xffffffffu, rs1, 2);
    const float inv0 = 1.f / rs0, inv1 = 1.f / rs1;

    const int r0 = n0 + mr + g;
    const int r1 = r0 + 8;
    float* o0 = out + (qrow0 + r0) * 384 + ns * NSLC + 2 * c;
    float* o1 = out + (qrow0 + r1) * 384 + ns * NSLC + 2 * c;
#pragma unroll
    for (int nt = 0; nt < 24; nt++) {
        if (r0 < NN) *(float2*)(o0 + 8 * nt) = make_float2(d[nt][0] * inv0, d[nt][1] * inv0);
        if (r1 < NN) *(float2*)(o1 + 8 * nt) = make_float2(d[nt][2] * inv1, d[nt][3] * inv1);
    }
}

// ===========================================================================
// Kernel 3: time-attention weight + broadcast add (in place on out).
// ===========================================================================
__global__ __launch_bounds__(256) void k_time(
    const float* __restrict__ x, const float* __restrict__ Win,
    float* __restrict__ out)
{
    const int wid = threadIdx.x >> 5, lane = threadIdx.x & 31;
    const long node = (long)blockIdx.x * 8 + wid;
    __shared__ float qs[8][17];

    const float* xl = x + node * 384 + 368;
    float* dat = out + node * 384;

    if (lane < 16) {
        float q = 0.f;
#pragma unroll
        for (int d = 0; d < 16; d++) q += xl[d] * Win[d * 16 + lane];
        qs[wid][lane] = q;
    }
    __syncwarp();

    float att = -1e30f;
    if (lane < 24) {
        float a = 0.f;
#pragma unroll
        for (int d = 0; d < 16; d++) a += qs[wid][d] * dat[lane * 16 + d];
        att = a;
    }
    float mx = att;
#pragma unroll
    for (int m = 16; m >= 1; m >>= 1)
        mx = fmaxf(mx, __shfl_xor_sync(0xffffffffu, mx, m));
    float e = (lane < 24) ? __expf(att - mx) : 0.f;
    float s = e;
#pragma unroll
    for (int m = 16; m >= 1; m >>= 1)
        s += __shfl_xor_sync(0xffffffffu, s, m);
    float wgt = e / s;

#pragma unroll
    for (int jj = 0; jj < 12; jj++) {
        int i = lane + 32 * jj;
        int t = i >> 4;
        float wt = __shfl_sync(0xffffffffu, wgt, t);
        dat[i] += wt;
    }
}

// ===========================================================================
extern "C" void kernel_launch(void* const* d_in, const int* in_sizes, int n_in,
                              void* d_out, int out_size)
{
    const float* x      = (const float*)d_in[0];
    const float* Wq     = (const float*)d_in[1];
    const float* bq     = (const float*)d_in[2];
    const float* Wk     = (const float*)d_in[3];
    const float* bk     = (const float*)d_in[4];
    const float* g0     = (const float*)d_in[5];
    const float* be0    = (const float*)d_in[6];
    const float* g1     = (const float*)d_in[7];
    const float* be1    = (const float*)d_in[8];
    const float* normal = (const float*)d_in[9];
    const float* Win    = (const float*)d_in[10];
    float* out = (float*)d_out;

    cudaFuncSetAttribute(k_proj_mma, cudaFuncAttributeMaxDynamicSharedMemorySize, KP_SMEM);
    cudaFuncSetAttribute(k_attn_mma, cudaFuncAttributeMaxDynamicSharedMemorySize, SMEM_SZ);

    k_proj_mma<<<(BATCH * NN) / 64, 256, KP_SMEM>>>(x, Wq, bq, Wk, bk, g0, be0, g1, be1);
    k_transpose<<<dim3(64, 12), 256>>>(normal);
    k_attn_mma<<<dim3(16, 2, BATCH), 256, SMEM_SZ>>>(out);
    k_time<<<(BATCH * NN) / 8, 256>>>(x, Win, out);
}